// round 6
// baseline (speedup 1.0000x reference)
#include <cuda_runtime.h>
#include <cuda_fp16.h>
#include <cstdint>

#define B_    16
#define CIN_  256
#define COUT_ 256
#define H_    64
#define W_    64
#define SDIM_ 512

#define MOD_SCALE (1.0f / 48.0f)
#define SCALE2    (1.0f / 2304.0f)

// scratch
__device__ float g_s[B_ * CIN_];
__device__ float g_demod[B_ * COUT_];
__device__ float g_wsq[COUT_ * CIN_];
// fp16 modulated weights [b][tap][co][ci] (ci fastest) — 18.9 MB
__device__ __half g_wth[(size_t)B_ * 9 * COUT_ * CIN_];
// fp16 NHWC activations [b][h][w][ci] — 33.5 MB
__device__ __half g_xh[(size_t)B_ * H_ * W_ * CIN_];

__device__ __forceinline__ uint32_t h2_bits(__half2 h) {
    union { __half2 h; uint32_t u; } c;
    c.h = h;
    return c.u;
}

// ---------------------------------------------------------------------------
// K1: style projection
__global__ void k_style_proj(const float* __restrict__ style,
                             const float* __restrict__ style_w,
                             const float* __restrict__ style_b) {
    __shared__ float st[SDIM_];
    const int b = blockIdx.x, ci = threadIdx.x;
    for (int k = threadIdx.x; k < SDIM_; k += blockDim.x)
        st[k] = style[b * SDIM_ + k];
    __syncthreads();
    float acc = style_b[ci];
    #pragma unroll 8
    for (int k = 0; k < SDIM_; k++)
        acc += st[k] * style_w[k * CIN_ + ci];
    g_s[b * CIN_ + ci] = acc;
}

// K2: wsq[co][ci] = sum_k w^2
__global__ void k_wsq(const float* __restrict__ weight) {
    const int idx = blockIdx.x * blockDim.x + threadIdx.x;
    const float* wp = weight + (size_t)idx * 9;
    float s = 0.f;
    #pragma unroll
    for (int k = 0; k < 9; k++) { float v = wp[k]; s += v * v; }
    g_wsq[idx] = s;
}

// K3: demod
__global__ void k_demod() {
    __shared__ float s2[CIN_];
    const int b = blockIdx.x, co = threadIdx.x;
    float sv = g_s[b * CIN_ + threadIdx.x];
    s2[threadIdx.x] = sv * sv;
    __syncthreads();
    float acc = 0.f;
    const float* wq = g_wsq + co * CIN_;
    #pragma unroll 8
    for (int ci = 0; ci < CIN_; ci++)
        acc += s2[ci] * wq[ci];
    g_demod[b * COUT_ + co] = rsqrtf(acc * SCALE2 + 1e-8f);
}

// ---------------------------------------------------------------------------
// K4: g_wth[b][tap][co][ci] = fp16(w * s * MOD_SCALE * demod), half2 writes
__global__ void k_wmod_h(const float* __restrict__ weight) {
    __shared__ float ws[32][289];
    __shared__ float ssm[32], dsm[32];
    const int b = blockIdx.z, ci0 = blockIdx.x * 32, co0 = blockIdx.y * 32;
    const int tid = threadIdx.x;

    for (int i = tid; i < 2304; i += 256) {
        int row = i / 72, q = i - row * 72;
        const float4 v = *(const float4*)(weight + (size_t)(co0 + row) * 2304 + (size_t)ci0 * 9 + q * 4);
        ws[row][q * 4 + 0] = v.x;
        ws[row][q * 4 + 1] = v.y;
        ws[row][q * 4 + 2] = v.z;
        ws[row][q * 4 + 3] = v.w;
    }
    if (tid < 32) {
        ssm[tid] = g_s[b * CIN_ + ci0 + tid];
        dsm[tid] = MOD_SCALE * g_demod[b * COUT_ + co0 + tid];
    }
    __syncthreads();

    for (int i = tid; i < 4608; i += 256) {
        int ci2 = i & 15, co = (i >> 4) & 31, tap = i >> 9;
        int ci = ci2 * 2;
        float d = dsm[co];
        float v0 = ws[co][ci * 9 + tap] * ssm[ci] * d;
        float v1 = ws[co][(ci + 1) * 9 + tap] * ssm[ci + 1] * d;
        *(__half2*)&g_wth[((size_t)(b * 9 + tap) * COUT_ + co0 + co) * CIN_ + ci0 + ci] =
            __floats2half2_rn(v0, v1);
    }
}

// ---------------------------------------------------------------------------
// K4b: NCHW fp32 -> NHWC fp16.  Block 256: 4 h-rows. Thread t: w = t&63.
__global__ void k_xcvt(const float* __restrict__ x) {
    const int b = blockIdx.y;
    const int h = blockIdx.x * 4 + (threadIdx.x >> 6);
    const int w = threadIdx.x & 63;
    const float* xp = x + ((size_t)b * CIN_ * H_ + h) * W_ + w;
    __half* op = g_xh + (((size_t)b * H_ + h) * W_ + w) * CIN_;
    #pragma unroll 2
    for (int ci0 = 0; ci0 < CIN_; ci0 += 8) {
        uint32_t u[4];
        #pragma unroll
        for (int j = 0; j < 4; j++) {
            float v0 = xp[(size_t)(ci0 + 2 * j) * (H_ * W_)];
            float v1 = xp[(size_t)(ci0 + 2 * j + 1) * (H_ * W_)];
            u[j] = h2_bits(__floats2half2_rn(v0, v1));
        }
        *(uint4*)(op + ci0) = make_uint4(u[0], u[1], u[2], u[3]);
    }
}

// ---------------------------------------------------------------------------
// K5: double-buffered implicit-GEMM conv, mma.sync.m16n8k16 fp16.
// Block: 128 co x (2 rows x 64 cols). 8 warps = 4M x 2N. KC=16 ci per chunk.
#define KC 16
#define XS_BYTES (264 * KC * 2)        // 8448
#define WS_BYTES (9 * 128 * KC * 2)    // 36864
#define STAGE_BYTES (XS_BYTES + WS_BYTES)
#define SMEM_TOTAL (2 * STAGE_BYTES)   // 90624

__global__ void __launch_bounds__(256, 2)
k_conv(float* __restrict__ out) {
    extern __shared__ char smem[];
    const uint32_t smem_u = (uint32_t)__cvta_generic_to_shared(smem);

    const int tid = threadIdx.x;
    const int lane = tid & 31, wid = tid >> 5;
    const int warp_m = wid >> 1, warp_n = wid & 1;
    const int g = lane >> 2, tig = lane & 3;

    const int h0 = blockIdx.x * 2;
    const int co_base = blockIdx.y * 128;
    const int b = blockIdx.z;

    const __half* wtb = g_wth + (size_t)b * 9 * COUT_ * CIN_ + (size_t)co_base * CIN_;
    const __half* xhb = g_xh + (size_t)b * H_ * W_ * CIN_;

    float acc[2][8][4];
    #pragma unroll
    for (int mt = 0; mt < 2; mt++)
        #pragma unroll
        for (int nt = 0; nt < 8; nt++)
            #pragma unroll
            for (int q = 0; q < 4; q++) acc[mt][nt][q] = 0.f;

    auto issue = [&](int c, int s) {
        const int ci0 = c * KC;
        const uint32_t xs_u = smem_u + s * STAGE_BYTES;
        const uint32_t ws_u = xs_u + XS_BYTES;
        // A: wsT[tap][co][ci] <- g_wth, 2304 x 16B
        #pragma unroll
        for (int j = 0; j < 9; j++) {
            int u = tid + j * 256;
            int row = u >> 1, hl = u & 1;         // row = tap*128+co
            int tap = row >> 7, co = row & 127;
            const __half* src = wtb + ((size_t)tap * COUT_ + co) * CIN_ + ci0 + hl * 8;
            asm volatile("cp.async.ca.shared.global [%0], [%1], 16;"
                         :: "r"(ws_u + row * 32 + hl * 16), "l"(src));
        }
        // B: xs[px][ci] <- g_xh NHWC, 528 x 16B, zero-fill halo
        #pragma unroll
        for (int k = 0; k < 3; k++) {
            int i = tid + k * 256;
            if (i < 528) {
                int px = i >> 1, hl = i & 1;
                int r = px / 66, cc = px - r * 66;
                int gh = h0 - 1 + r, gw = cc - 1;
                bool ok = ((unsigned)gh < (unsigned)H_) && ((unsigned)gw < (unsigned)W_);
                int ghc = ok ? gh : 0, gwc = ok ? gw : 0;
                const __half* src = xhb + ((size_t)ghc * W_ + gwc) * CIN_ + ci0 + hl * 8;
                int sz = ok ? 16 : 0;
                asm volatile("cp.async.ca.shared.global [%0], [%1], 16, %2;"
                             :: "r"(xs_u + px * 32 + hl * 16), "l"(src), "r"(sz));
            }
        }
        asm volatile("cp.async.commit_group;");
    };

    issue(0, 0);

    for (int c = 0; c < CIN_ / KC; c++) {
        if (c + 1 < CIN_ / KC) {
            issue(c + 1, (c + 1) & 1);
            asm volatile("cp.async.wait_group 1;" ::: "memory");
        } else {
            asm volatile("cp.async.wait_group 0;" ::: "memory");
        }
        __syncthreads();

        const __half* xs = (const __half*)(smem + (c & 1) * STAGE_BYTES);
        const __half* wsT = (const __half*)(smem + (c & 1) * STAGE_BYTES + XS_BYTES);

        #pragma unroll
        for (int tap = 0; tap < 9; tap++) {
            const int dh = tap / 3, dw = tap - dh * 3;
            const __half* wr = &wsT[tap * 128 * KC];

            uint32_t a[2][4];
            #pragma unroll
            for (int mt = 0; mt < 2; mt++) {
                int m = warp_m * 32 + mt * 16;
                a[mt][0] = *(const uint32_t*)&wr[(m + g) * KC + tig * 2];
                a[mt][1] = *(const uint32_t*)&wr[(m + g + 8) * KC + tig * 2];
                a[mt][2] = *(const uint32_t*)&wr[(m + g) * KC + tig * 2 + 8];
                a[mt][3] = *(const uint32_t*)&wr[(m + g + 8) * KC + tig * 2 + 8];
            }
            const int rowoff = (warp_n + dh) * 66 + dw;
            #pragma unroll
            for (int nt = 0; nt < 8; nt++) {
                int cb = nt * 8 + g;
                uint32_t b0 = *(const uint32_t*)&xs[(rowoff + cb) * KC + tig * 2];
                uint32_t b1 = *(const uint32_t*)&xs[(rowoff + cb) * KC + tig * 2 + 8];
                #pragma unroll
                for (int mt = 0; mt < 2; mt++) {
                    asm volatile(
                        "mma.sync.aligned.m16n8k16.row.col.f32.f16.f16.f32 "
                        "{%0,%1,%2,%3}, {%4,%5,%6,%7}, {%8,%9}, {%0,%1,%2,%3};\n"
                        : "+f"(acc[mt][nt][0]), "+f"(acc[mt][nt][1]),
                          "+f"(acc[mt][nt][2]), "+f"(acc[mt][nt][3])
                        : "r"(a[mt][0]), "r"(a[mt][1]), "r"(a[mt][2]), "r"(a[mt][3]),
                          "r"(b0), "r"(b1));
                }
            }
        }
        __syncthreads();
    }

    // epilogue
    const int h = h0 + warp_n;
    #pragma unroll
    for (int mt = 0; mt < 2; mt++) {
        int co_lo = co_base + warp_m * 32 + mt * 16 + g;
        #pragma unroll
        for (int nt = 0; nt < 8; nt++) {
            int w = nt * 8 + tig * 2;
            float* p0 = out + (((size_t)(b * COUT_ + co_lo)) * H_ + h) * W_ + w;
            *(float2*)p0 = make_float2(acc[mt][nt][0], acc[mt][nt][1]);
            float* p1 = p0 + (size_t)8 * H_ * W_;
            *(float2*)p1 = make_float2(acc[mt][nt][2], acc[mt][nt][3]);
        }
    }
}

// ---------------------------------------------------------------------------
extern "C" void kernel_launch(void* const* d_in, const int* in_sizes, int n_in,
                              void* d_out, int out_size) {
    const float* x       = (const float*)d_in[0];
    const float* style   = (const float*)d_in[1];
    const float* weight  = (const float*)d_in[2];
    const float* style_w = (const float*)d_in[3];
    const float* style_b = (const float*)d_in[4];
    float* out = (float*)d_out;

    cudaFuncSetAttribute(k_conv, cudaFuncAttributeMaxDynamicSharedMemorySize, SMEM_TOTAL);

    k_style_proj<<<B_, CIN_>>>(style, style_w, style_b);
    k_wsq<<<COUT_, CIN_>>>(weight);
    k_demod<<<B_, COUT_>>>();

    dim3 gw(8, 8, B_);
    k_wmod_h<<<gw, 256>>>(weight);

    dim3 gx(H_ / 4, B_);
    k_xcvt<<<gx, 256>>>(x);

    dim3 gc(H_ / 2, COUT_ / 128, B_);
    k_conv<<<gc, 256, SMEM_TOTAL>>>(out);
}

// round 7
// speedup vs baseline: 1.2811x; 1.2811x over previous
#include <cuda_runtime.h>
#include <cuda_fp16.h>
#include <cstdint>

#define B_    16
#define CIN_  256
#define COUT_ 256
#define H_    64
#define W_    64
#define SDIM_ 512

#define MOD_SCALE (1.0f / 48.0f)
#define SCALE2    (1.0f / 2304.0f)

// scratch
__device__ float g_s[B_ * CIN_];
__device__ float g_demod[B_ * COUT_];
__device__ float g_wsq[COUT_ * CIN_];
// fp16 modulated weights [b][tap][co][ci] (ci fastest) — 18.9 MB
__device__ __half g_wth[(size_t)B_ * 9 * COUT_ * CIN_];
// fp16 NHWC activations [b][h][w][ci] — 33.5 MB
__device__ __half g_xh[(size_t)B_ * H_ * W_ * CIN_];

__device__ __forceinline__ uint32_t h2_bits(__half2 h) {
    union { __half2 h; uint32_t u; } c;
    c.h = h;
    return c.u;
}

// ---------------------------------------------------------------------------
// K1: style projection
__global__ void k_style_proj(const float* __restrict__ style,
                             const float* __restrict__ style_w,
                             const float* __restrict__ style_b) {
    __shared__ float st[SDIM_];
    const int b = blockIdx.x, ci = threadIdx.x;
    for (int k = threadIdx.x; k < SDIM_; k += blockDim.x)
        st[k] = style[b * SDIM_ + k];
    __syncthreads();
    float acc = style_b[ci];
    #pragma unroll 8
    for (int k = 0; k < SDIM_; k++)
        acc += st[k] * style_w[k * CIN_ + ci];
    g_s[b * CIN_ + ci] = acc;
}

// K2: wsq
__global__ void k_wsq(const float* __restrict__ weight) {
    const int idx = blockIdx.x * blockDim.x + threadIdx.x;
    const float* wp = weight + (size_t)idx * 9;
    float s = 0.f;
    #pragma unroll
    for (int k = 0; k < 9; k++) { float v = wp[k]; s += v * v; }
    g_wsq[idx] = s;
}

// K3: demod
__global__ void k_demod() {
    __shared__ float s2[CIN_];
    const int b = blockIdx.x, co = threadIdx.x;
    float sv = g_s[b * CIN_ + threadIdx.x];
    s2[threadIdx.x] = sv * sv;
    __syncthreads();
    float acc = 0.f;
    const float* wq = g_wsq + co * CIN_;
    #pragma unroll 8
    for (int ci = 0; ci < CIN_; ci++)
        acc += s2[ci] * wq[ci];
    g_demod[b * COUT_ + co] = rsqrtf(acc * SCALE2 + 1e-8f);
}

// ---------------------------------------------------------------------------
// K4: g_wth[b][tap][co][ci] = fp16(w * s * MOD_SCALE * demod)
__global__ void k_wmod_h(const float* __restrict__ weight) {
    __shared__ float ws[32][289];
    __shared__ float ssm[32], dsm[32];
    const int b = blockIdx.z, ci0 = blockIdx.x * 32, co0 = blockIdx.y * 32;
    const int tid = threadIdx.x;

    for (int i = tid; i < 2304; i += 256) {
        int row = i / 72, q = i - row * 72;
        const float4 v = *(const float4*)(weight + (size_t)(co0 + row) * 2304 + (size_t)ci0 * 9 + q * 4);
        ws[row][q * 4 + 0] = v.x;
        ws[row][q * 4 + 1] = v.y;
        ws[row][q * 4 + 2] = v.z;
        ws[row][q * 4 + 3] = v.w;
    }
    if (tid < 32) {
        ssm[tid] = g_s[b * CIN_ + ci0 + tid];
        dsm[tid] = MOD_SCALE * g_demod[b * COUT_ + co0 + tid];
    }
    __syncthreads();

    for (int i = tid; i < 4608; i += 256) {
        int ci2 = i & 15, co = (i >> 4) & 31, tap = i >> 9;
        int ci = ci2 * 2;
        float d = dsm[co];
        float v0 = ws[co][ci * 9 + tap] * ssm[ci] * d;
        float v1 = ws[co][(ci + 1) * 9 + tap] * ssm[ci + 1] * d;
        *(__half2*)&g_wth[((size_t)(b * 9 + tap) * COUT_ + co0 + co) * CIN_ + ci0 + ci] =
            __floats2half2_rn(v0, v1);
    }
}

// ---------------------------------------------------------------------------
// K4b: NCHW fp32 -> NHWC fp16
__global__ void k_xcvt(const float* __restrict__ x) {
    const int b = blockIdx.y;
    const int h = blockIdx.x * 4 + (threadIdx.x >> 6);
    const int w = threadIdx.x & 63;
    const float* xp = x + ((size_t)b * CIN_ * H_ + h) * W_ + w;
    __half* op = g_xh + (((size_t)b * H_ + h) * W_ + w) * CIN_;
    #pragma unroll 2
    for (int ci0 = 0; ci0 < CIN_; ci0 += 8) {
        uint32_t u[4];
        #pragma unroll
        for (int j = 0; j < 4; j++) {
            float v0 = xp[(size_t)(ci0 + 2 * j) * (H_ * W_)];
            float v1 = xp[(size_t)(ci0 + 2 * j + 1) * (H_ * W_)];
            u[j] = h2_bits(__floats2half2_rn(v0, v1));
        }
        *(uint4*)(op + ci0) = make_uint4(u[0], u[1], u[2], u[3]);
    }
}

// ---------------------------------------------------------------------------
// K5: double-buffered implicit-GEMM conv, mma.sync.m16n8k16 fp16,
// bank-conflict-free XOR-swizzled smem (chunk = row*32 + (hl^bit2(row))*16).
#define KC 16
#define XS_BYTES (264 * KC * 2)        // 8448
#define WS_BYTES (9 * 128 * KC * 2)    // 36864
#define STAGE_BYTES (XS_BYTES + WS_BYTES)
#define SMEM_TOTAL (2 * STAGE_BYTES)   // 90624

__global__ void __launch_bounds__(256, 2)
k_conv(float* __restrict__ out) {
    extern __shared__ char smem[];
    const uint32_t smem_u = (uint32_t)__cvta_generic_to_shared(smem);

    const int tid = threadIdx.x;
    const int lane = tid & 31, wid = tid >> 5;
    const int warp_m = wid >> 1, warp_n = wid & 1;
    const int g = lane >> 2, tig = lane & 3;

    const int h0 = blockIdx.x * 2;
    const int co_base = blockIdx.y * 128;
    const int b = blockIdx.z;

    const __half* wtb = g_wth + (size_t)b * 9 * COUT_ * CIN_ + (size_t)co_base * CIN_;
    const __half* xhb = g_xh + (size_t)b * H_ * W_ * CIN_;

    // ---- staging geometry (closed form) ----
    const int co_t = tid >> 1, hl = tid & 1;
    const uint32_t swz = (uint32_t)((hl ^ ((co_t >> 2) & 1)) * 16);
    // A: slot j stages (tap=j, co=co_t, half hl): gmem off = j*65536 + co_t*256 + hl*8
    //    smem off = j*4096 + co_t*32 + swz
    // B: slot k stages px = co_t + k*128 (half hl)
    uint32_t b_goff[3];
    int b_sz[3];
    #pragma unroll
    for (int k = 0; k < 3; k++) {
        int px = co_t + k * 128;
        int r = px / 66, cc = px - r * 66;
        int gh = h0 - 1 + r, gw = cc - 1;
        bool ok = ((unsigned)gh < (unsigned)H_) && ((unsigned)gw < (unsigned)W_);
        int ghc = ok ? gh : 0, gwc = ok ? gw : 0;
        b_goff[k] = (uint32_t)((ghc * W_ + gwc) * CIN_ + hl * 8);
        b_sz[k] = ok ? 16 : 0;
    }

    float acc[2][8][4];
    #pragma unroll
    for (int mt = 0; mt < 2; mt++)
        #pragma unroll
        for (int nt = 0; nt < 8; nt++)
            #pragma unroll
            for (int q = 0; q < 4; q++) acc[mt][nt][q] = 0.f;

    auto issue = [&](int c, int s) {
        const uint32_t stage = smem_u + s * STAGE_BYTES;
        const uint32_t wsu = stage + XS_BYTES + co_t * 32 + swz;
        const __half* asrc = wtb + co_t * CIN_ + hl * 8 + c * KC;
        #pragma unroll
        for (int j = 0; j < 9; j++) {
            asm volatile("cp.async.cg.shared.global [%0], [%1], 16;"
                         :: "r"(wsu + j * 4096), "l"(asrc + (size_t)j * 65536));
        }
        const uint32_t xsu = stage + co_t * 32 + swz;
        const __half* bsrc = xhb + c * KC;
        #pragma unroll
        for (int k = 0; k < 2; k++) {
            asm volatile("cp.async.cg.shared.global [%0], [%1], 16, %2;"
                         :: "r"(xsu + k * 4096), "l"(bsrc + b_goff[k]), "r"(b_sz[k]));
        }
        if (tid < 16) {
            asm volatile("cp.async.cg.shared.global [%0], [%1], 16, %2;"
                         :: "r"(xsu + 2 * 4096), "l"(bsrc + b_goff[2]), "r"(b_sz[2]));
        }
        asm volatile("cp.async.commit_group;");
    };

    issue(0, 0);

    const int sA = ((g >> 2) & 1) * 8;   // A-frag swizzle (half units)

    for (int c = 0; c < CIN_ / KC; c++) {
        if (c + 1 < CIN_ / KC) {
            issue(c + 1, (c + 1) & 1);
            asm volatile("cp.async.wait_group 1;" ::: "memory");
        } else {
            asm volatile("cp.async.wait_group 0;" ::: "memory");
        }
        __syncthreads();

        const __half* xs = (const __half*)(smem + (c & 1) * STAGE_BYTES);
        const __half* wsT = (const __half*)(smem + (c & 1) * STAGE_BYTES + XS_BYTES);

        #pragma unroll
        for (int tap = 0; tap < 9; tap++) {
            const int dh = tap / 3, dw = tap - dh * 3;

            uint32_t a[2][4];
            #pragma unroll
            for (int mt = 0; mt < 2; mt++) {
                int ro = (tap * 128 + warp_m * 32 + mt * 16 + g) * KC;
                a[mt][0] = *(const uint32_t*)&wsT[ro + sA + tig * 2];
                a[mt][1] = *(const uint32_t*)&wsT[ro + 128 + sA + tig * 2];
                a[mt][2] = *(const uint32_t*)&wsT[ro + (8 - sA) + tig * 2];
                a[mt][3] = *(const uint32_t*)&wsT[ro + 128 + (8 - sA) + tig * 2];
            }
            const int rowoff = (warp_n + dh) * 66 + dw;
            const int sB = (((rowoff + g) >> 2) & 1) * 8;
            #pragma unroll
            for (int nt = 0; nt < 8; nt++) {
                int po = (rowoff + nt * 8 + g) * KC;
                uint32_t b0 = *(const uint32_t*)&xs[po + sB + tig * 2];
                uint32_t b1 = *(const uint32_t*)&xs[po + (8 - sB) + tig * 2];
                #pragma unroll
                for (int mt = 0; mt < 2; mt++) {
                    asm volatile(
                        "mma.sync.aligned.m16n8k16.row.col.f32.f16.f16.f32 "
                        "{%0,%1,%2,%3}, {%4,%5,%6,%7}, {%8,%9}, {%0,%1,%2,%3};\n"
                        : "+f"(acc[mt][nt][0]), "+f"(acc[mt][nt][1]),
                          "+f"(acc[mt][nt][2]), "+f"(acc[mt][nt][3])
                        : "r"(a[mt][0]), "r"(a[mt][1]), "r"(a[mt][2]), "r"(a[mt][3]),
                          "r"(b0), "r"(b1));
                }
            }
        }
        __syncthreads();
    }

    // epilogue
    const int h = h0 + warp_n;
    #pragma unroll
    for (int mt = 0; mt < 2; mt++) {
        int co_lo = co_base + warp_m * 32 + mt * 16 + g;
        #pragma unroll
        for (int nt = 0; nt < 8; nt++) {
            int w = nt * 8 + tig * 2;
            float* p0 = out + (((size_t)(b * COUT_ + co_lo)) * H_ + h) * W_ + w;
            *(float2*)p0 = make_float2(acc[mt][nt][0], acc[mt][nt][1]);
            float* p1 = p0 + (size_t)8 * H_ * W_;
            *(float2*)p1 = make_float2(acc[mt][nt][2], acc[mt][nt][3]);
        }
    }
}

// ---------------------------------------------------------------------------
extern "C" void kernel_launch(void* const* d_in, const int* in_sizes, int n_in,
                              void* d_out, int out_size) {
    const float* x       = (const float*)d_in[0];
    const float* style   = (const float*)d_in[1];
    const float* weight  = (const float*)d_in[2];
    const float* style_w = (const float*)d_in[3];
    const float* style_b = (const float*)d_in[4];
    float* out = (float*)d_out;

    cudaFuncSetAttribute(k_conv, cudaFuncAttributeMaxDynamicSharedMemorySize, SMEM_TOTAL);

    k_style_proj<<<B_, CIN_>>>(style, style_w, style_b);
    k_wsq<<<COUT_, CIN_>>>(weight);
    k_demod<<<B_, COUT_>>>();

    dim3 gw(8, 8, B_);
    k_wmod_h<<<gw, 256>>>(weight);

    dim3 gx(H_ / 4, B_);
    k_xcvt<<<gx, 256>>>(x);

    dim3 gc(H_ / 2, COUT_ / 128, B_);
    k_conv<<<gc, 256, SMEM_TOTAL>>>(out);
}

// round 9
// speedup vs baseline: 1.3187x; 1.0294x over previous
#include <cuda_runtime.h>
#include <cuda_fp16.h>
#include <cstdint>

#define B_    16
#define CIN_  256
#define COUT_ 256
#define H_    64
#define W_    64
#define SDIM_ 512

#define MOD_SCALE (1.0f / 48.0f)
#define SCALE2    (1.0f / 2304.0f)

// scratch
__device__ float g_s[B_ * CIN_];
__device__ float g_demod[B_ * COUT_];
__device__ float g_wsq[COUT_ * CIN_];
__device__ __half g_wth[(size_t)B_ * 9 * COUT_ * CIN_];   // [b][tap][co][ci]
__device__ __half g_xh[(size_t)B_ * H_ * W_ * CIN_];      // NHWC fp16

__device__ __forceinline__ uint32_t h2_bits(__half2 h) {
    union { __half2 h; uint32_t u; } c;
    c.h = h;
    return c.u;
}

// ---------------------------------------------------------------------------
// K_wsq: wsq[co][ci] = sum_k w^2
__global__ void k_wsq(const float* __restrict__ weight) {
    const int idx = blockIdx.x * blockDim.x + threadIdx.x;
    const float* wp = weight + (size_t)idx * 9;
    float s = 0.f;
    #pragma unroll
    for (int k = 0; k < 9; k++) { float v = wp[k]; s += v * v; }
    g_wsq[idx] = s;
}

// K_sd: fused style projection + demod. grid = B_, block = 256.
__global__ void k_sproj_demod(const float* __restrict__ style,
                              const float* __restrict__ style_w,
                              const float* __restrict__ style_b) {
    __shared__ float st[SDIM_];
    __shared__ float s2[CIN_];
    const int b = blockIdx.x, tid = threadIdx.x;
    for (int k = tid; k < SDIM_; k += 256)
        st[k] = style[b * SDIM_ + k];
    __syncthreads();
    float acc = style_b[tid];
    #pragma unroll 8
    for (int k = 0; k < SDIM_; k++)
        acc += st[k] * style_w[k * CIN_ + tid];
    g_s[b * CIN_ + tid] = acc;
    s2[tid] = acc * acc;
    __syncthreads();
    float acc2 = 0.f;
    const float* wq = g_wsq + tid * CIN_;
    #pragma unroll 8
    for (int ci = 0; ci < CIN_; ci++)
        acc2 += s2[ci] * wq[ci];
    g_demod[b * COUT_ + tid] = rsqrtf(acc2 * SCALE2 + 1e-8f);
}

// ---------------------------------------------------------------------------
// K_wmod: streaming build of g_wth[b][tap][co][ci].
__global__ void k_wmod_h(const float* __restrict__ weight) {
    const int tid = threadIdx.x;
    const int co = blockIdx.x * 8 + (tid >> 5);
    const int oct = tid & 31;
    const int b = blockIdx.y;

    const float dm = MOD_SCALE * g_demod[b * COUT_ + co];
    float sv[8];
    {
        const float4* s4 = (const float4*)(g_s + b * CIN_ + oct * 8);
        float4 sa = s4[0], sb2 = s4[1];
        sv[0] = sa.x * dm; sv[1] = sa.y * dm; sv[2] = sa.z * dm; sv[3] = sa.w * dm;
        sv[4] = sb2.x * dm; sv[5] = sb2.y * dm; sv[6] = sb2.z * dm; sv[7] = sb2.w * dm;
    }
    float w[72];
    {
        const float4* wp = (const float4*)(weight + (size_t)co * 2304 + oct * 72);
        #pragma unroll
        for (int i = 0; i < 18; i++) {
            float4 v = wp[i];
            w[i * 4 + 0] = v.x; w[i * 4 + 1] = v.y; w[i * 4 + 2] = v.z; w[i * 4 + 3] = v.w;
        }
    }
    __half* ob = g_wth + (size_t)(b * 9) * COUT_ * CIN_ + (size_t)co * CIN_ + oct * 8;
    #pragma unroll
    for (int tap = 0; tap < 9; tap++) {
        uint32_t u[4];
        #pragma unroll
        for (int j2 = 0; j2 < 4; j2++) {
            float v0 = w[(2 * j2) * 9 + tap] * sv[2 * j2];
            float v1 = w[(2 * j2 + 1) * 9 + tap] * sv[2 * j2 + 1];
            u[j2] = h2_bits(__floats2half2_rn(v0, v1));
        }
        *(uint4*)(ob + (size_t)tap * COUT_ * CIN_) = make_uint4(u[0], u[1], u[2], u[3]);
    }
}

// ---------------------------------------------------------------------------
// K_xcvt: NCHW fp32 -> NHWC fp16
__global__ void k_xcvt(const float* __restrict__ x) {
    const int b = blockIdx.y;
    const int h = blockIdx.x * 4 + (threadIdx.x >> 6);
    const int w = threadIdx.x & 63;
    const float* xp = x + ((size_t)b * CIN_ * H_ + h) * W_ + w;
    __half* op = g_xh + (((size_t)b * H_ + h) * W_ + w) * CIN_;
    #pragma unroll 2
    for (int ci0 = 0; ci0 < CIN_; ci0 += 8) {
        uint32_t u[4];
        #pragma unroll
        for (int j = 0; j < 4; j++) {
            float v0 = xp[(size_t)(ci0 + 2 * j) * (H_ * W_)];
            float v1 = xp[(size_t)(ci0 + 2 * j + 1) * (H_ * W_)];
            u[j] = h2_bits(__floats2half2_rn(v0, v1));
        }
        *(uint4*)(op + ci0) = make_uint4(u[0], u[1], u[2], u[3]);
    }
}

// ---------------------------------------------------------------------------
// K_conv: double-buffered implicit-GEMM, mma.sync.m16n8k16 fp16,
// XOR-swizzled smem + ldmatrix.x4 (distinct A/B lane geometry).
#define KC 16
#define XS_BYTES (264 * KC * 2)        // 8448
#define WS_BYTES (9 * 128 * KC * 2)    // 36864
#define STAGE_BYTES (XS_BYTES + WS_BYTES)
#define SMEM_TOTAL (2 * STAGE_BYTES)   // 90624

__global__ void __launch_bounds__(256, 2)
k_conv(float* __restrict__ out) {
    extern __shared__ char smem[];
    const uint32_t smem_u = (uint32_t)__cvta_generic_to_shared(smem);

    const int tid = threadIdx.x;
    const int lane = tid & 31, wid = tid >> 5;
    const int warp_m = wid >> 1, warp_n = wid & 1;
    const int g = lane >> 2, tig = lane & 3;

    const int h0 = blockIdx.x * 2;
    const int co_base = blockIdx.y * 128;
    const int b = blockIdx.z;

    const __half* wtb = g_wth + (size_t)b * 9 * COUT_ * CIN_ + (size_t)co_base * CIN_;
    const __half* xhb = g_xh + (size_t)b * H_ * W_ * CIN_;

    // staging geometry (closed form)
    const int co_t = tid >> 1, hl = tid & 1;
    const uint32_t swz = (uint32_t)((hl ^ ((co_t >> 2) & 1)) * 16);
    uint32_t b_goff[3];
    int b_sz[3];
    #pragma unroll
    for (int k = 0; k < 3; k++) {
        int px = co_t + k * 128;
        int r = px / 66, cc = px - r * 66;
        int gh = h0 - 1 + r, gw = cc - 1;
        bool ok = ((unsigned)gh < (unsigned)H_) && ((unsigned)gw < (unsigned)W_);
        int ghc = ok ? gh : 0, gwc = ok ? gw : 0;
        b_goff[k] = (uint32_t)((ghc * W_ + gwc) * CIN_ + hl * 8);
        b_sz[k] = ok ? 16 : 0;
    }

    float acc[2][8][4];
    #pragma unroll
    for (int mt = 0; mt < 2; mt++)
        #pragma unroll
        for (int nt = 0; nt < 8; nt++)
            #pragma unroll
            for (int q = 0; q < 4; q++) acc[mt][nt][q] = 0.f;

    auto issue = [&](int c, int s) {
        const uint32_t stage = smem_u + s * STAGE_BYTES;
        const uint32_t wsu = stage + XS_BYTES + co_t * 32 + swz;
        const __half* asrc = wtb + co_t * CIN_ + hl * 8 + c * KC;
        #pragma unroll
        for (int j = 0; j < 9; j++) {
            asm volatile("cp.async.cg.shared.global [%0], [%1], 16;"
                         :: "r"(wsu + j * 4096), "l"(asrc + (size_t)j * 65536));
        }
        const uint32_t xsu = stage + co_t * 32 + swz;
        const __half* bsrc = xhb + c * KC;
        #pragma unroll
        for (int k = 0; k < 2; k++) {
            asm volatile("cp.async.cg.shared.global [%0], [%1], 16, %2;"
                         :: "r"(xsu + k * 4096), "l"(bsrc + b_goff[k]), "r"(b_sz[k]));
        }
        if (tid < 16) {
            asm volatile("cp.async.cg.shared.global [%0], [%1], 16, %2;"
                         :: "r"(xsu + 2 * 4096), "l"(bsrc + b_goff[2]), "r"(b_sz[2]));
        }
        asm volatile("cp.async.commit_group;");
    };

    issue(0, 0);

    // ldmatrix lane geometry
    // A (m16k16 row-major): mat0 = rows0-7/k0-7, mat1 = rows8-15/k0-7,
    //                       mat2 = rows0-7/k8-15, mat3 = rows8-15/k8-15
    const int laneRowA = (lane & 7) + (((lane >> 3) & 1) << 3);
    const uint32_t kA = (uint32_t)(((lane >> 4) & 1) << 4);
    // B (n16k16, rows = pixels): mat0 = px0-7/k0-7, mat1 = px0-7/k8-15,
    //                            mat2 = px8-15/k0-7, mat3 = px8-15/k8-15
    const int laneRowB = (lane & 7) + ((lane >> 4) << 3);
    const uint32_t kB = (uint32_t)(((lane >> 3) & 1) << 4);

    for (int c = 0; c < CIN_ / KC; c++) {
        if (c + 1 < CIN_ / KC) {
            issue(c + 1, (c + 1) & 1);
            asm volatile("cp.async.wait_group 1;" ::: "memory");
        } else {
            asm volatile("cp.async.wait_group 0;" ::: "memory");
        }
        __syncthreads();

        const uint32_t xs_u2 = smem_u + (c & 1) * STAGE_BYTES;
        const uint32_t ws_u2 = xs_u2 + XS_BYTES;

        #pragma unroll
        for (int tap = 0; tap < 9; tap++) {
            const int dh = tap / 3, dw = tap - dh * 3;

            uint32_t a[2][4];
            #pragma unroll
            for (int mt = 0; mt < 2; mt++) {
                int rowA = tap * 128 + warp_m * 32 + mt * 16 + laneRowA;
                uint32_t addrA = ws_u2 + rowA * 32 + (kA ^ ((rowA & 4) << 2));
                asm volatile("ldmatrix.sync.aligned.m8n8.x4.shared.b16 "
                             "{%0,%1,%2,%3}, [%4];"
                             : "=r"(a[mt][0]), "=r"(a[mt][1]),
                               "=r"(a[mt][2]), "=r"(a[mt][3])
                             : "r"(addrA));
            }
            const int rowoff = (warp_n + dh) * 66 + dw;
            #pragma unroll
            for (int ntp = 0; ntp < 4; ntp++) {
                int pxl = rowoff + ntp * 16 + laneRowB;
                uint32_t addrB = xs_u2 + pxl * 32 + (kB ^ ((pxl & 4) << 2));
                uint32_t bq[4];
                asm volatile("ldmatrix.sync.aligned.m8n8.x4.shared.b16 "
                             "{%0,%1,%2,%3}, [%4];"
                             : "=r"(bq[0]), "=r"(bq[1]), "=r"(bq[2]), "=r"(bq[3])
                             : "r"(addrB));
                #pragma unroll
                for (int half = 0; half < 2; half++) {
                    int nt = ntp * 2 + half;
                    #pragma unroll
                    for (int mt = 0; mt < 2; mt++) {
                        asm volatile(
                            "mma.sync.aligned.m16n8k16.row.col.f32.f16.f16.f32 "
                            "{%0,%1,%2,%3}, {%4,%5,%6,%7}, {%8,%9}, {%0,%1,%2,%3};\n"
                            : "+f"(acc[mt][nt][0]), "+f"(acc[mt][nt][1]),
                              "+f"(acc[mt][nt][2]), "+f"(acc[mt][nt][3])
                            : "r"(a[mt][0]), "r"(a[mt][1]), "r"(a[mt][2]), "r"(a[mt][3]),
                              "r"(bq[half * 2]), "r"(bq[half * 2 + 1]));
                    }
                }
            }
        }
        __syncthreads();
    }

    // epilogue
    const int h = h0 + warp_n;
    #pragma unroll
    for (int mt = 0; mt < 2; mt++) {
        int co_lo = co_base + warp_m * 32 + mt * 16 + g;
        #pragma unroll
        for (int nt = 0; nt < 8; nt++) {
            int w = nt * 8 + tig * 2;
            float* p0 = out + (((size_t)(b * COUT_ + co_lo)) * H_ + h) * W_ + w;
            *(float2*)p0 = make_float2(acc[mt][nt][0], acc[mt][nt][1]);
            float* p1 = p0 + (size_t)8 * H_ * W_;
            *(float2*)p1 = make_float2(acc[mt][nt][2], acc[mt][nt][3]);
        }
    }
}

// ---------------------------------------------------------------------------
extern "C" void kernel_launch(void* const* d_in, const int* in_sizes, int n_in,
                              void* d_out, int out_size) {
    const float* x       = (const float*)d_in[0];
    const float* style   = (const float*)d_in[1];
    const float* weight  = (const float*)d_in[2];
    const float* style_w = (const float*)d_in[3];
    const float* style_b = (const float*)d_in[4];
    float* out = (float*)d_out;

    cudaFuncSetAttribute(k_conv, cudaFuncAttributeMaxDynamicSharedMemorySize, SMEM_TOTAL);

    k_wsq<<<COUT_, CIN_>>>(weight);
    k_sproj_demod<<<B_, 256>>>(style, style_w, style_b);

    dim3 gw(32, B_);
    k_wmod_h<<<gw, 256>>>(weight);

    dim3 gx(H_ / 4, B_);
    k_xcvt<<<gx, 256>>>(x);

    dim3 gc(H_ / 2, COUT_ / 128, B_);
    k_conv<<<gc, 256, SMEM_TOTAL>>>(out);
}

// round 10
// speedup vs baseline: 1.3501x; 1.0238x over previous
#include <cuda_runtime.h>
#include <cuda_fp16.h>
#include <cstdint>

#define B_    16
#define CIN_  256
#define COUT_ 256
#define H_    64
#define W_    64
#define SDIM_ 512

#define MOD_SCALE (1.0f / 48.0f)
#define SCALE2    (1.0f / 2304.0f)

// scratch
__device__ float g_s[B_ * CIN_];
__device__ float g_demod[B_ * COUT_];
__device__ float g_wsq[COUT_ * CIN_];
__device__ __half g_wth[(size_t)B_ * 9 * COUT_ * CIN_];   // [b][tap][co][ci]
__device__ __half g_xh[(size_t)B_ * H_ * W_ * CIN_];      // NHWC fp16

__device__ __forceinline__ uint32_t h2_bits(__half2 h) {
    union { __half2 h; uint32_t u; } c;
    c.h = h;
    return c.u;
}

// ---------------------------------------------------------------------------
// K_wsq: wsq[co][ci] = sum_k w^2
__global__ void k_wsq(const float* __restrict__ weight) {
    const int idx = blockIdx.x * blockDim.x + threadIdx.x;
    const float* wp = weight + (size_t)idx * 9;
    float s = 0.f;
    #pragma unroll
    for (int k = 0; k < 9; k++) { float v = wp[k]; s += v * v; }
    g_wsq[idx] = s;
}

// K_sd: fused style projection + demod. grid = B_, block = 256.
__global__ void k_sproj_demod(const float* __restrict__ style,
                              const float* __restrict__ style_w,
                              const float* __restrict__ style_b) {
    __shared__ float st[SDIM_];
    __shared__ float s2[CIN_];
    const int b = blockIdx.x, tid = threadIdx.x;
    for (int k = tid; k < SDIM_; k += 256)
        st[k] = style[b * SDIM_ + k];
    __syncthreads();
    float acc = style_b[tid];
    #pragma unroll 8
    for (int k = 0; k < SDIM_; k++)
        acc += st[k] * style_w[k * CIN_ + tid];
    g_s[b * CIN_ + tid] = acc;
    s2[tid] = acc * acc;
    __syncthreads();
    float acc2 = 0.f;
    const float* wq = g_wsq + tid * CIN_;
    #pragma unroll 8
    for (int ci = 0; ci < CIN_; ci++)
        acc2 += s2[ci] * wq[ci];
    g_demod[b * COUT_ + tid] = rsqrtf(acc2 * SCALE2 + 1e-8f);
}

// ---------------------------------------------------------------------------
// K_wmod: streaming build of g_wth[b][tap][co][ci].
__global__ void k_wmod_h(const float* __restrict__ weight) {
    const int tid = threadIdx.x;
    const int co = blockIdx.x * 8 + (tid >> 5);
    const int oct = tid & 31;
    const int b = blockIdx.y;

    const float dm = MOD_SCALE * g_demod[b * COUT_ + co];
    float sv[8];
    {
        const float4* s4 = (const float4*)(g_s + b * CIN_ + oct * 8);
        float4 sa = s4[0], sb2 = s4[1];
        sv[0] = sa.x * dm; sv[1] = sa.y * dm; sv[2] = sa.z * dm; sv[3] = sa.w * dm;
        sv[4] = sb2.x * dm; sv[5] = sb2.y * dm; sv[6] = sb2.z * dm; sv[7] = sb2.w * dm;
    }
    float w[72];
    {
        const float4* wp = (const float4*)(weight + (size_t)co * 2304 + oct * 72);
        #pragma unroll
        for (int i = 0; i < 18; i++) {
            float4 v = wp[i];
            w[i * 4 + 0] = v.x; w[i * 4 + 1] = v.y; w[i * 4 + 2] = v.z; w[i * 4 + 3] = v.w;
        }
    }
    __half* ob = g_wth + (size_t)(b * 9) * COUT_ * CIN_ + (size_t)co * CIN_ + oct * 8;
    #pragma unroll
    for (int tap = 0; tap < 9; tap++) {
        uint32_t u[4];
        #pragma unroll
        for (int j2 = 0; j2 < 4; j2++) {
            float v0 = w[(2 * j2) * 9 + tap] * sv[2 * j2];
            float v1 = w[(2 * j2 + 1) * 9 + tap] * sv[2 * j2 + 1];
            u[j2] = h2_bits(__floats2half2_rn(v0, v1));
        }
        *(uint4*)(ob + (size_t)tap * COUT_ * CIN_) = make_uint4(u[0], u[1], u[2], u[3]);
    }
}

// ---------------------------------------------------------------------------
// K_xcvt: NCHW fp32 -> NHWC fp16 via smem transpose.
// Block = (64 ci x 64 w) tile of one (b, h) row. grid (4, 64, 16).
// Reads: 256B-coalesced rows. Writes: 128B-contiguous NHWC chunks.
#define XPAD 72   // row stride in halves (144B: 16B-aligned for uint4 reads)
__global__ void __launch_bounds__(256)
k_xcvt(const float* __restrict__ x) {
    __shared__ __half xsp[64 * XPAD];
    const int b = blockIdx.z, h = blockIdx.y, ci0 = blockIdx.x * 64;
    const int tid = threadIdx.x;
    const float* xp = x + ((size_t)(b * CIN_ + ci0) * H_ + h) * W_;

    #pragma unroll
    for (int i = 0; i < 16; i++) {
        int idx = tid + i * 256;
        int ci = idx >> 6, w = idx & 63;
        xsp[w * XPAD + ci] = __float2half_rn(xp[(size_t)ci * (H_ * W_) + w]);
    }
    __syncthreads();

    __half* op = g_xh + (((size_t)b * H_ + h) * W_) * CIN_ + ci0;
    #pragma unroll
    for (int i = 0; i < 2; i++) {
        int idx = tid + i * 256;
        int w = idx >> 3, j = idx & 7;
        uint4 v = *(const uint4*)&xsp[w * XPAD + j * 8];
        *(uint4*)(op + (size_t)w * CIN_ + j * 8) = v;
    }
}

// ---------------------------------------------------------------------------
// K_conv: double-buffered implicit-GEMM, mma.sync.m16n8k16 fp16,
// XOR-swizzled smem + ldmatrix.x4 (distinct A/B lane geometry).
#define KC 16
#define XS_BYTES (264 * KC * 2)        // 8448
#define WS_BYTES (9 * 128 * KC * 2)    // 36864
#define STAGE_BYTES (XS_BYTES + WS_BYTES)
#define SMEM_TOTAL (2 * STAGE_BYTES)   // 90624

__global__ void __launch_bounds__(256, 2)
k_conv(float* __restrict__ out) {
    extern __shared__ char smem[];
    const uint32_t smem_u = (uint32_t)__cvta_generic_to_shared(smem);

    const int tid = threadIdx.x;
    const int lane = tid & 31, wid = tid >> 5;
    const int warp_m = wid >> 1, warp_n = wid & 1;
    const int g = lane >> 2, tig = lane & 3;

    const int h0 = blockIdx.x * 2;
    const int co_base = blockIdx.y * 128;
    const int b = blockIdx.z;

    const __half* wtb = g_wth + (size_t)b * 9 * COUT_ * CIN_ + (size_t)co_base * CIN_;
    const __half* xhb = g_xh + (size_t)b * H_ * W_ * CIN_;

    // staging geometry (closed form)
    const int co_t = tid >> 1, hl = tid & 1;
    const uint32_t swz = (uint32_t)((hl ^ ((co_t >> 2) & 1)) * 16);
    uint32_t b_goff[3];
    int b_sz[3];
    #pragma unroll
    for (int k = 0; k < 3; k++) {
        int px = co_t + k * 128;
        int r = px / 66, cc = px - r * 66;
        int gh = h0 - 1 + r, gw = cc - 1;
        bool ok = ((unsigned)gh < (unsigned)H_) && ((unsigned)gw < (unsigned)W_);
        int ghc = ok ? gh : 0, gwc = ok ? gw : 0;
        b_goff[k] = (uint32_t)((ghc * W_ + gwc) * CIN_ + hl * 8);
        b_sz[k] = ok ? 16 : 0;
    }

    float acc[2][8][4];
    #pragma unroll
    for (int mt = 0; mt < 2; mt++)
        #pragma unroll
        for (int nt = 0; nt < 8; nt++)
            #pragma unroll
            for (int q = 0; q < 4; q++) acc[mt][nt][q] = 0.f;

    auto issue = [&](int c, int s) {
        const uint32_t stage = smem_u + s * STAGE_BYTES;
        const uint32_t wsu = stage + XS_BYTES + co_t * 32 + swz;
        const __half* asrc = wtb + co_t * CIN_ + hl * 8 + c * KC;
        #pragma unroll
        for (int j = 0; j < 9; j++) {
            asm volatile("cp.async.cg.shared.global [%0], [%1], 16;"
                         :: "r"(wsu + j * 4096), "l"(asrc + (size_t)j * 65536));
        }
        const uint32_t xsu = stage + co_t * 32 + swz;
        const __half* bsrc = xhb + c * KC;
        #pragma unroll
        for (int k = 0; k < 2; k++) {
            asm volatile("cp.async.cg.shared.global [%0], [%1], 16, %2;"
                         :: "r"(xsu + k * 4096), "l"(bsrc + b_goff[k]), "r"(b_sz[k]));
        }
        if (tid < 16) {
            asm volatile("cp.async.cg.shared.global [%0], [%1], 16, %2;"
                         :: "r"(xsu + 2 * 4096), "l"(bsrc + b_goff[2]), "r"(b_sz[2]));
        }
        asm volatile("cp.async.commit_group;");
    };

    issue(0, 0);

    // ldmatrix lane geometry
    const int laneRowA = (lane & 7) + (((lane >> 3) & 1) << 3);
    const uint32_t kA = (uint32_t)(((lane >> 4) & 1) << 4);
    const int laneRowB = (lane & 7) + ((lane >> 4) << 3);
    const uint32_t kB = (uint32_t)(((lane >> 3) & 1) << 4);

    for (int c = 0; c < CIN_ / KC; c++) {
        if (c + 1 < CIN_ / KC) {
            issue(c + 1, (c + 1) & 1);
            asm volatile("cp.async.wait_group 1;" ::: "memory");
        } else {
            asm volatile("cp.async.wait_group 0;" ::: "memory");
        }
        __syncthreads();

        const uint32_t xs_u2 = smem_u + (c & 1) * STAGE_BYTES;
        const uint32_t ws_u2 = xs_u2 + XS_BYTES;

        #pragma unroll
        for (int tap = 0; tap < 9; tap++) {
            const int dh = tap / 3, dw = tap - dh * 3;

            uint32_t a[2][4];
            #pragma unroll
            for (int mt = 0; mt < 2; mt++) {
                int rowA = tap * 128 + warp_m * 32 + mt * 16 + laneRowA;
                uint32_t addrA = ws_u2 + rowA * 32 + (kA ^ ((rowA & 4) << 2));
                asm volatile("ldmatrix.sync.aligned.m8n8.x4.shared.b16 "
                             "{%0,%1,%2,%3}, [%4];"
                             : "=r"(a[mt][0]), "=r"(a[mt][1]),
                               "=r"(a[mt][2]), "=r"(a[mt][3])
                             : "r"(addrA));
            }
            const int rowoff = (warp_n + dh) * 66 + dw;
            #pragma unroll
            for (int ntp = 0; ntp < 4; ntp++) {
                int pxl = rowoff + ntp * 16 + laneRowB;
                uint32_t addrB = xs_u2 + pxl * 32 + (kB ^ ((pxl & 4) << 2));
                uint32_t bq[4];
                asm volatile("ldmatrix.sync.aligned.m8n8.x4.shared.b16 "
                             "{%0,%1,%2,%3}, [%4];"
                             : "=r"(bq[0]), "=r"(bq[1]), "=r"(bq[2]), "=r"(bq[3])
                             : "r"(addrB));
                #pragma unroll
                for (int half = 0; half < 2; half++) {
                    int nt = ntp * 2 + half;
                    #pragma unroll
                    for (int mt = 0; mt < 2; mt++) {
                        asm volatile(
                            "mma.sync.aligned.m16n8k16.row.col.f32.f16.f16.f32 "
                            "{%0,%1,%2,%3}, {%4,%5,%6,%7}, {%8,%9}, {%0,%1,%2,%3};\n"
                            : "+f"(acc[mt][nt][0]), "+f"(acc[mt][nt][1]),
                              "+f"(acc[mt][nt][2]), "+f"(acc[mt][nt][3])
                            : "r"(a[mt][0]), "r"(a[mt][1]), "r"(a[mt][2]), "r"(a[mt][3]),
                              "r"(bq[half * 2]), "r"(bq[half * 2 + 1]));
                    }
                }
            }
        }
        __syncthreads();
    }

    // epilogue
    const int h = h0 + warp_n;
    #pragma unroll
    for (int mt = 0; mt < 2; mt++) {
        int co_lo = co_base + warp_m * 32 + mt * 16 + g;
        #pragma unroll
        for (int nt = 0; nt < 8; nt++) {
            int w = nt * 8 + tig * 2;
            float* p0 = out + (((size_t)(b * COUT_ + co_lo)) * H_ + h) * W_ + w;
            *(float2*)p0 = make_float2(acc[mt][nt][0], acc[mt][nt][1]);
            float* p1 = p0 + (size_t)8 * H_ * W_;
            *(float2*)p1 = make_float2(acc[mt][nt][2], acc[mt][nt][3]);
        }
    }
}

// ---------------------------------------------------------------------------
extern "C" void kernel_launch(void* const* d_in, const int* in_sizes, int n_in,
                              void* d_out, int out_size) {
    const float* x       = (const float*)d_in[0];
    const float* style   = (const float*)d_in[1];
    const float* weight  = (const float*)d_in[2];
    const float* style_w = (const float*)d_in[3];
    const float* style_b = (const float*)d_in[4];
    float* out = (float*)d_out;

    cudaFuncSetAttribute(k_conv, cudaFuncAttributeMaxDynamicSharedMemorySize, SMEM_TOTAL);

    dim3 gx(4, 64, 16);
    k_xcvt<<<gx, 256>>>(x);

    k_wsq<<<COUT_, CIN_>>>(weight);
    k_sproj_demod<<<B_, 256>>>(style, style_w, style_b);

    dim3 gw(32, B_);
    k_wmod_h<<<gw, 256>>>(weight);

    dim3 gc(H_ / 2, COUT_ / 128, B_);
    k_conv<<<gc, 256, SMEM_TOTAL>>>(out);
}

// round 12
// speedup vs baseline: 1.3683x; 1.0134x over previous
#include <cuda_runtime.h>
#include <cuda_fp16.h>
#include <cstdint>

#define B_    16
#define CIN_  256
#define COUT_ 256
#define H_    64
#define W_    64
#define SDIM_ 512

#define MOD_SCALE (1.0f / 48.0f)
#define SCALE2    (1.0f / 2304.0f)

// scratch
__device__ float g_s[B_ * CIN_];
__device__ float g_demod[B_ * COUT_];
__device__ float g_wsq[COUT_ * CIN_];
__device__ __half g_wth[(size_t)9 * COUT_ * CIN_];        // [tap][co][ci], batch-free, 4.7MB
__device__ __half g_xh[(size_t)B_ * H_ * W_ * CIN_];      // NHWC fp16 of x * s[b,ci]

__device__ __forceinline__ uint32_t h2_bits(__half2 h) {
    union { __half2 h; uint32_t u; } c;
    c.h = h;
    return c.u;
}

// ---------------------------------------------------------------------------
// K_wsq: wsq[co][ci] = sum_k w^2
__global__ void k_wsq(const float* __restrict__ weight) {
    const int idx = blockIdx.x * blockDim.x + threadIdx.x;
    const float* wp = weight + (size_t)idx * 9;
    float s = 0.f;
    #pragma unroll
    for (int k = 0; k < 9; k++) { float v = wp[k]; s += v * v; }
    g_wsq[idx] = s;
}

// K_sd: fused style projection + demod. grid = B_, block = 256.
__global__ void k_sproj_demod(const float* __restrict__ style,
                              const float* __restrict__ style_w,
                              const float* __restrict__ style_b) {
    __shared__ float st[SDIM_];
    __shared__ float s2[CIN_];
    const int b = blockIdx.x, tid = threadIdx.x;
    for (int k = tid; k < SDIM_; k += 256)
        st[k] = style[b * SDIM_ + k];
    __syncthreads();
    float acc = style_b[tid];
    #pragma unroll 8
    for (int k = 0; k < SDIM_; k++)
        acc += st[k] * style_w[k * CIN_ + tid];
    g_s[b * CIN_ + tid] = acc;
    s2[tid] = acc * acc;
    __syncthreads();
    float acc2 = 0.f;
    const float* wq = g_wsq + tid * CIN_;
    #pragma unroll 8
    for (int ci = 0; ci < CIN_; ci++)
        acc2 += s2[ci] * wq[ci];
    g_demod[b * COUT_ + tid] = rsqrtf(acc2 * SCALE2 + 1e-8f);
}

// ---------------------------------------------------------------------------
// K_wcvt: batch-free fp16 weight convert: g_wth[tap][co][ci] = fp16(w[co][ci][tap]).
// grid (32), block 256: co = bx*8 + tid>>5, oct = lane.
__global__ void k_wcvt(const float* __restrict__ weight) {
    const int tid = threadIdx.x;
    const int co = blockIdx.x * 8 + (tid >> 5);
    const int oct = tid & 31;

    float w[72];
    {
        const float4* wp = (const float4*)(weight + (size_t)co * 2304 + oct * 72);
        #pragma unroll
        for (int i = 0; i < 18; i++) {
            float4 v = wp[i];
            w[i * 4 + 0] = v.x; w[i * 4 + 1] = v.y; w[i * 4 + 2] = v.z; w[i * 4 + 3] = v.w;
        }
    }
    __half* ob = g_wth + (size_t)co * CIN_ + oct * 8;
    #pragma unroll
    for (int tap = 0; tap < 9; tap++) {
        uint32_t u[4];
        #pragma unroll
        for (int j2 = 0; j2 < 4; j2++) {
            u[j2] = h2_bits(__floats2half2_rn(w[(2 * j2) * 9 + tap],
                                              w[(2 * j2 + 1) * 9 + tap]));
        }
        *(uint4*)(ob + (size_t)tap * COUT_ * CIN_) = make_uint4(u[0], u[1], u[2], u[3]);
    }
}

// ---------------------------------------------------------------------------
// K_xcvt: NCHW fp32 -> NHWC fp16, folding in the modulation s[b,ci].
// Block = (64 ci x 64 w) tile of one (b, h) row. grid (4, 64, 16).
#define XPAD 72
__global__ void __launch_bounds__(256)
k_xcvt(const float* __restrict__ x) {
    __shared__ __half xsp[64 * XPAD];
    __shared__ float sS[64];
    const int b = blockIdx.z, h = blockIdx.y, ci0 = blockIdx.x * 64;
    const int tid = threadIdx.x;
    const float* xp = x + ((size_t)(b * CIN_ + ci0) * H_ + h) * W_;

    if (tid < 64) sS[tid] = g_s[b * CIN_ + ci0 + tid];
    __syncthreads();

    #pragma unroll
    for (int i = 0; i < 16; i++) {
        int idx = tid + i * 256;
        int ci = idx >> 6, w = idx & 63;
        xsp[w * XPAD + ci] = __float2half_rn(xp[(size_t)ci * (H_ * W_) + w] * sS[ci]);
    }
    __syncthreads();

    __half* op = g_xh + (((size_t)b * H_ + h) * W_) * CIN_ + ci0;
    #pragma unroll
    for (int i = 0; i < 2; i++) {
        int idx = tid + i * 256;
        int w = idx >> 3, j = idx & 7;
        uint4 v = *(const uint4*)&xsp[w * XPAD + j * 8];
        *(uint4*)(op + (size_t)w * CIN_ + j * 8) = v;
    }
}

// ---------------------------------------------------------------------------
// K_conv: double-buffered implicit-GEMM, mma.sync.m16n8k16 fp16,
// XOR-swizzled smem + ldmatrix.x4; demod applied in epilogue.
#define KC 16
#define XS_BYTES (264 * KC * 2)        // 8448
#define WS_BYTES (9 * 128 * KC * 2)    // 36864
#define STAGE_BYTES (XS_BYTES + WS_BYTES)
#define SMEM_TOTAL (2 * STAGE_BYTES)   // 90624

__global__ void __launch_bounds__(256, 2)
k_conv(float* __restrict__ out) {
    extern __shared__ char smem[];
    const uint32_t smem_u = (uint32_t)__cvta_generic_to_shared(smem);

    const int tid = threadIdx.x;
    const int lane = tid & 31, wid = tid >> 5;
    const int warp_m = wid >> 1, warp_n = wid & 1;
    const int g = lane >> 2, tig = lane & 3;

    const int h0 = blockIdx.x * 2;
    const int co_base = blockIdx.y * 128;
    const int b = blockIdx.z;

    const __half* wtb = g_wth + (size_t)co_base * CIN_;   // batch-free
    const __half* xhb = g_xh + (size_t)b * H_ * W_ * CIN_;

    // staging geometry (closed form)
    const int co_t = tid >> 1, hl = tid & 1;
    const uint32_t swz = (uint32_t)((hl ^ ((co_t >> 2) & 1)) * 16);
    uint32_t b_goff[3];
    int b_sz[3];
    #pragma unroll
    for (int k = 0; k < 3; k++) {
        int px = co_t + k * 128;
        int r = px / 66, cc = px - r * 66;
        int gh = h0 - 1 + r, gw = cc - 1;
        bool ok = ((unsigned)gh < (unsigned)H_) && ((unsigned)gw < (unsigned)W_);
        int ghc = ok ? gh : 0, gwc = ok ? gw : 0;
        b_goff[k] = (uint32_t)((ghc * W_ + gwc) * CIN_ + hl * 8);
        b_sz[k] = ok ? 16 : 0;
    }

    float acc[2][8][4];
    #pragma unroll
    for (int mt = 0; mt < 2; mt++)
        #pragma unroll
        for (int nt = 0; nt < 8; nt++)
            #pragma unroll
            for (int q = 0; q < 4; q++) acc[mt][nt][q] = 0.f;

    auto issue = [&](int c, int s) {
        const uint32_t stage = smem_u + s * STAGE_BYTES;
        const uint32_t wsu = stage + XS_BYTES + co_t * 32 + swz;
        const __half* asrc = wtb + co_t * CIN_ + hl * 8 + c * KC;
        #pragma unroll
        for (int j = 0; j < 9; j++) {
            asm volatile("cp.async.cg.shared.global [%0], [%1], 16;"
                         :: "r"(wsu + j * 4096), "l"(asrc + (size_t)j * 65536));
        }
        const uint32_t xsu = stage + co_t * 32 + swz;
        const __half* bsrc = xhb + c * KC;
        #pragma unroll
        for (int k = 0; k < 2; k++) {
            asm volatile("cp.async.cg.shared.global [%0], [%1], 16, %2;"
                         :: "r"(xsu + k * 4096), "l"(bsrc + b_goff[k]), "r"(b_sz[k]));
        }
        if (tid < 16) {
            asm volatile("cp.async.cg.shared.global [%0], [%1], 16, %2;"
                         :: "r"(xsu + 2 * 4096), "l"(bsrc + b_goff[2]), "r"(b_sz[2]));
        }
        asm volatile("cp.async.commit_group;");
    };

    issue(0, 0);

    // ldmatrix lane geometry (A vs B distinct)
    const int laneRowA = (lane & 7) + (((lane >> 3) & 1) << 3);
    const uint32_t kA = (uint32_t)(((lane >> 4) & 1) << 4);
    const int laneRowB = (lane & 7) + ((lane >> 4) << 3);
    const uint32_t kB = (uint32_t)(((lane >> 3) & 1) << 4);

    for (int c = 0; c < CIN_ / KC; c++) {
        if (c + 1 < CIN_ / KC) {
            issue(c + 1, (c + 1) & 1);
            asm volatile("cp.async.wait_group 1;" ::: "memory");
        } else {
            asm volatile("cp.async.wait_group 0;" ::: "memory");
        }
        __syncthreads();

        const uint32_t xs_u2 = smem_u + (c & 1) * STAGE_BYTES;
        const uint32_t ws_u2 = xs_u2 + XS_BYTES;

        #pragma unroll
        for (int tap = 0; tap < 9; tap++) {
            const int dh = tap / 3, dw = tap - dh * 3;

            uint32_t a[2][4];
            #pragma unroll
            for (int mt = 0; mt < 2; mt++) {
                int rowA = tap * 128 + warp_m * 32 + mt * 16 + laneRowA;
                uint32_t addrA = ws_u2 + rowA * 32 + (kA ^ ((rowA & 4) << 2));
                asm volatile("ldmatrix.sync.aligned.m8n8.x4.shared.b16 "
                             "{%0,%1,%2,%3}, [%4];"
                             : "=r"(a[mt][0]), "=r"(a[mt][1]),
                               "=r"(a[mt][2]), "=r"(a[mt][3])
                             : "r"(addrA));
            }
            const int rowoff = (warp_n + dh) * 66 + dw;
            #pragma unroll
            for (int ntp = 0; ntp < 4; ntp++) {
                int pxl = rowoff + ntp * 16 + laneRowB;
                uint32_t addrB = xs_u2 + pxl * 32 + (kB ^ ((pxl & 4) << 2));
                uint32_t bq[4];
                asm volatile("ldmatrix.sync.aligned.m8n8.x4.shared.b16 "
                             "{%0,%1,%2,%3}, [%4];"
                             : "=r"(bq[0]), "=r"(bq[1]), "=r"(bq[2]), "=r"(bq[3])
                             : "r"(addrB));
                #pragma unroll
                for (int half = 0; half < 2; half++) {
                    int nt = ntp * 2 + half;
                    #pragma unroll
                    for (int mt = 0; mt < 2; mt++) {
                        asm volatile(
                            "mma.sync.aligned.m16n8k16.row.col.f32.f16.f16.f32 "
                            "{%0,%1,%2,%3}, {%4,%5,%6,%7}, {%8,%9}, {%0,%1,%2,%3};\n"
                            : "+f"(acc[mt][nt][0]), "+f"(acc[mt][nt][1]),
                              "+f"(acc[mt][nt][2]), "+f"(acc[mt][nt][3])
                            : "r"(a[mt][0]), "r"(a[mt][1]), "r"(a[mt][2]), "r"(a[mt][3]),
                              "r"(bq[half * 2]), "r"(bq[half * 2 + 1]));
                    }
                }
            }
        }
        __syncthreads();
    }

    // epilogue: apply mod_scale * demod[b, co] here
    const int h = h0 + warp_n;
    #pragma unroll
    for (int mt = 0; mt < 2; mt++) {
        int co_lo = co_base + warp_m * 32 + mt * 16 + g;
        float f0 = MOD_SCALE * __ldg(&g_demod[b * COUT_ + co_lo]);
        float f1 = MOD_SCALE * __ldg(&g_demod[b * COUT_ + co_lo + 8]);
        #pragma unroll
        for (int nt = 0; nt < 8; nt++) {
            int w = nt * 8 + tig * 2;
            float* p0 = out + (((size_t)(b * COUT_ + co_lo)) * H_ + h) * W_ + w;
            *(float2*)p0 = make_float2(acc[mt][nt][0] * f0, acc[mt][nt][1] * f0);
            float* p1 = p0 + (size_t)8 * H_ * W_;
            *(float2*)p1 = make_float2(acc[mt][nt][2] * f1, acc[mt][nt][3] * f1);
        }
    }
}

// ---------------------------------------------------------------------------
extern "C" void kernel_launch(void* const* d_in, const int* in_sizes, int n_in,
                              void* d_out, int out_size) {
    const float* x       = (const float*)d_in[0];
    const float* style   = (const float*)d_in[1];
    const float* weight  = (const float*)d_in[2];
    const float* style_w = (const float*)d_in[3];
    const float* style_b = (const float*)d_in[4];
    float* out = (float*)d_out;

    cudaFuncSetAttribute(k_conv, cudaFuncAttributeMaxDynamicSharedMemorySize, SMEM_TOTAL);

    k_wsq<<<COUT_, CIN_>>>(weight);
    k_wcvt<<<32, 256>>>(weight);
    k_sproj_demod<<<B_, 256>>>(style, style_w, style_b);

    dim3 gx(4, 64, 16);
    k_xcvt<<<gx, 256>>>(x);

    dim3 gc(H_ / 2, COUT_ / 128, B_);
    k_conv<<<gc, 256, SMEM_TOTAL>>>(out);
}

// round 14
// speedup vs baseline: 1.3881x; 1.0145x over previous
#include <cuda_runtime.h>
#include <cuda_fp16.h>
#include <cstdint>

#define B_    16
#define CIN_  256
#define COUT_ 256
#define H_    64
#define W_    64
#define SDIM_ 512

#define MOD_SCALE (1.0f / 48.0f)
#define SCALE2    (1.0f / 2304.0f)

// scratch
__device__ float g_s[B_ * CIN_];
__device__ float g_demod[B_ * COUT_];
__device__ float g_wsq[COUT_ * CIN_];
__device__ __half g_wth[(size_t)9 * COUT_ * CIN_];        // [tap][co][ci], batch-free
__device__ __half g_xh[(size_t)B_ * H_ * W_ * CIN_];      // NHWC fp16 of x * s[b,ci]

__device__ __forceinline__ uint32_t h2_bits(__half2 h) {
    union { __half2 h; uint32_t u; } c;
    c.h = h;
    return c.u;
}

// ---------------------------------------------------------------------------
// K_wcvt: fused batch-free weight convert + wsq.
// thread = (co, 8-ci octet): w[72] in regs -> fp16 taps + sum-of-squares.
// grid (32), block 256.
__global__ void k_wcvt(const float* __restrict__ weight) {
    const int tid = threadIdx.x;
    const int co = blockIdx.x * 8 + (tid >> 5);
    const int oct = tid & 31;

    float w[72];
    {
        const float4* wp = (const float4*)(weight + (size_t)co * 2304 + oct * 72);
        #pragma unroll
        for (int i = 0; i < 18; i++) {
            float4 v = wp[i];
            w[i * 4 + 0] = v.x; w[i * 4 + 1] = v.y; w[i * 4 + 2] = v.z; w[i * 4 + 3] = v.w;
        }
    }
    // fp16 taps
    __half* ob = g_wth + (size_t)co * CIN_ + oct * 8;
    #pragma unroll
    for (int tap = 0; tap < 9; tap++) {
        uint32_t u[4];
        #pragma unroll
        for (int j2 = 0; j2 < 4; j2++) {
            u[j2] = h2_bits(__floats2half2_rn(w[(2 * j2) * 9 + tap],
                                              w[(2 * j2 + 1) * 9 + tap]));
        }
        *(uint4*)(ob + (size_t)tap * COUT_ * CIN_) = make_uint4(u[0], u[1], u[2], u[3]);
    }
    // wsq for the 8 ci this thread owns
    float q[8];
    #pragma unroll
    for (int j = 0; j < 8; j++) {
        float s = 0.f;
        #pragma unroll
        for (int t = 0; t < 9; t++) { float v = w[j * 9 + t]; s += v * v; }
        q[j] = s;
    }
    float4* wq = (float4*)(g_wsq + co * CIN_ + oct * 8);
    wq[0] = make_float4(q[0], q[1], q[2], q[3]);
    wq[1] = make_float4(q[4], q[5], q[6], q[7]);
}

// ---------------------------------------------------------------------------
// K_sd: fused style projection + demod. grid = B_, block = 256.
__global__ void k_sproj_demod(const float* __restrict__ style,
                              const float* __restrict__ style_w,
                              const float* __restrict__ style_b) {
    __shared__ float st[SDIM_];
    __shared__ float s2[CIN_];
    const int b = blockIdx.x, tid = threadIdx.x;
    for (int k = tid; k < SDIM_; k += 256)
        st[k] = style[b * SDIM_ + k];
    __syncthreads();
    float acc = style_b[tid];
    #pragma unroll 8
    for (int k = 0; k < SDIM_; k++)
        acc += st[k] * style_w[k * CIN_ + tid];
    g_s[b * CIN_ + tid] = acc;
    s2[tid] = acc * acc;
    __syncthreads();
    float acc2 = 0.f;
    const float* wq = g_wsq + tid * CIN_;
    #pragma unroll 8
    for (int ci = 0; ci < CIN_; ci++)
        acc2 += s2[ci] * wq[ci];
    g_demod[b * COUT_ + tid] = rsqrtf(acc2 * SCALE2 + 1e-8f);
}

// ---------------------------------------------------------------------------
// K_xcvt: NCHW fp32 -> NHWC fp16, folding in s[b,ci]; ci-pair half2 transpose.
// Block = (64 ci x 64 w) tile of one (b, h) row. grid (4, 64, 16).
// 4096 elements = 2048 ci-pairs = 8 per thread.
#define XPAD 72
__global__ void __launch_bounds__(256)
k_xcvt(const float* __restrict__ x) {
    __shared__ __half xsp[64 * XPAD];
    __shared__ float sS[64];
    const int b = blockIdx.z, h = blockIdx.y, ci0 = blockIdx.x * 64;
    const int tid = threadIdx.x;
    const float* xp = x + ((size_t)(b * CIN_ + ci0) * H_ + h) * W_;

    if (tid < 64) sS[tid] = g_s[b * CIN_ + ci0 + tid];
    __syncthreads();

    #pragma unroll
    for (int i = 0; i < 8; i++) {
        int idx = tid + i * 256;                // 0..2047
        int cp = idx >> 6, w = idx & 63;        // cp 0..31
        int ci = cp * 2;
        float v0 = xp[(size_t)ci * (H_ * W_) + w] * sS[ci];
        float v1 = xp[(size_t)(ci + 1) * (H_ * W_) + w] * sS[ci + 1];
        *(__half2*)&xsp[w * XPAD + ci] = __floats2half2_rn(v0, v1);
    }
    __syncthreads();

    __half* op = g_xh + (((size_t)b * H_ + h) * W_) * CIN_ + ci0;
    #pragma unroll
    for (int i = 0; i < 2; i++) {
        int idx = tid + i * 256;
        int w = idx >> 3, j = idx & 7;
        uint4 v = *(const uint4*)&xsp[w * XPAD + j * 8];
        *(uint4*)(op + (size_t)w * CIN_ + j * 8) = v;
    }
}

// ---------------------------------------------------------------------------
// K_conv: double-buffered implicit-GEMM, mma.sync.m16n8k16 fp16,
// XOR-swizzled smem + ldmatrix.x4; demod applied in epilogue.
#define KC 16
#define XS_BYTES (264 * KC * 2)        // 8448
#define WS_BYTES (9 * 128 * KC * 2)    // 36864
#define STAGE_BYTES (XS_BYTES + WS_BYTES)
#define SMEM_TOTAL (2 * STAGE_BYTES)   // 90624

__global__ void __launch_bounds__(256, 2)
k_conv(float* __restrict__ out) {
    extern __shared__ char smem[];
    const uint32_t smem_u = (uint32_t)__cvta_generic_to_shared(smem);

    const int tid = threadIdx.x;
    const int lane = tid & 31, wid = tid >> 5;
    const int warp_m = wid >> 1, warp_n = wid & 1;
    const int g = lane >> 2, tig = lane & 3;

    const int h0 = blockIdx.x * 2;
    const int co_base = blockIdx.y * 128;
    const int b = blockIdx.z;

    const __half* wtb = g_wth + (size_t)co_base * CIN_;   // batch-free
    const __half* xhb = g_xh + (size_t)b * H_ * W_ * CIN_;

    // staging geometry (closed form)
    const int co_t = tid >> 1, hl = tid & 1;
    const uint32_t swz = (uint32_t)((hl ^ ((co_t >> 2) & 1)) * 16);
    uint32_t b_goff[3];
    int b_sz[3];
    #pragma unroll
    for (int k = 0; k < 3; k++) {
        int px = co_t + k * 128;
        int r = px / 66, cc = px - r * 66;
        int gh = h0 - 1 + r, gw = cc - 1;
        bool ok = ((unsigned)gh < (unsigned)H_) && ((unsigned)gw < (unsigned)W_);
        int ghc = ok ? gh : 0, gwc = ok ? gw : 0;
        b_goff[k] = (uint32_t)((ghc * W_ + gwc) * CIN_ + hl * 8);
        b_sz[k] = ok ? 16 : 0;
    }

    float acc[2][8][4];
    #pragma unroll
    for (int mt = 0; mt < 2; mt++)
        #pragma unroll
        for (int nt = 0; nt < 8; nt++)
            #pragma unroll
            for (int q = 0; q < 4; q++) acc[mt][nt][q] = 0.f;

    auto issue = [&](int c, int s) {
        const uint32_t stage = smem_u + s * STAGE_BYTES;
        const uint32_t wsu = stage + XS_BYTES + co_t * 32 + swz;
        const __half* asrc = wtb + co_t * CIN_ + hl * 8 + c * KC;
        #pragma unroll
        for (int j = 0; j < 9; j++) {
            asm volatile("cp.async.cg.shared.global [%0], [%1], 16;"
                         :: "r"(wsu + j * 4096), "l"(asrc + (size_t)j * 65536));
        }
        const uint32_t xsu = stage + co_t * 32 + swz;
        const __half* bsrc = xhb + c * KC;
        #pragma unroll
        for (int k = 0; k < 2; k++) {
            asm volatile("cp.async.cg.shared.global [%0], [%1], 16, %2;"
                         :: "r"(xsu + k * 4096), "l"(bsrc + b_goff[k]), "r"(b_sz[k]));
        }
        if (tid < 16) {
            asm volatile("cp.async.cg.shared.global [%0], [%1], 16, %2;"
                         :: "r"(xsu + 2 * 4096), "l"(bsrc + b_goff[2]), "r"(b_sz[2]));
        }
        asm volatile("cp.async.commit_group;");
    };

    issue(0, 0);

    // ldmatrix lane geometry (A vs B distinct)
    const int laneRowA = (lane & 7) + (((lane >> 3) & 1) << 3);
    const uint32_t kA = (uint32_t)(((lane >> 4) & 1) << 4);
    const int laneRowB = (lane & 7) + ((lane >> 4) << 3);
    const uint32_t kB = (uint32_t)(((lane >> 3) & 1) << 4);

    for (int c = 0; c < CIN_ / KC; c++) {
        if (c + 1 < CIN_ / KC) {
            issue(c + 1, (c + 1) & 1);
            asm volatile("cp.async.wait_group 1;" ::: "memory");
        } else {
            asm volatile("cp.async.wait_group 0;" ::: "memory");
        }
        __syncthreads();

        const uint32_t xs_u2 = smem_u + (c & 1) * STAGE_BYTES;
        const uint32_t ws_u2 = xs_u2 + XS_BYTES;

        #pragma unroll
        for (int tap = 0; tap < 9; tap++) {
            const int dh = tap / 3, dw = tap - dh * 3;

            uint32_t a[2][4];
            #pragma unroll
            for (int mt = 0; mt < 2; mt++) {
                int rowA = tap * 128 + warp_m * 32 + mt * 16 + laneRowA;
                uint32_t addrA = ws_u2 + rowA * 32 + (kA ^ ((rowA & 4) << 2));
                asm volatile("ldmatrix.sync.aligned.m8n8.x4.shared.b16 "
                             "{%0,%1,%2,%3}, [%4];"
                             : "=r"(a[mt][0]), "=r"(a[mt][1]),
                               "=r"(a[mt][2]), "=r"(a[mt][3])
                             : "r"(addrA));
            }
            const int rowoff = (warp_n + dh) * 66 + dw;
            #pragma unroll
            for (int ntp = 0; ntp < 4; ntp++) {
                int pxl = rowoff + ntp * 16 + laneRowB;
                uint32_t addrB = xs_u2 + pxl * 32 + (kB ^ ((pxl & 4) << 2));
                uint32_t bq[4];
                asm volatile("ldmatrix.sync.aligned.m8n8.x4.shared.b16 "
                             "{%0,%1,%2,%3}, [%4];"
                             : "=r"(bq[0]), "=r"(bq[1]), "=r"(bq[2]), "=r"(bq[3])
                             : "r"(addrB));
                #pragma unroll
                for (int half = 0; half < 2; half++) {
                    int nt = ntp * 2 + half;
                    #pragma unroll
                    for (int mt = 0; mt < 2; mt++) {
                        asm volatile(
                            "mma.sync.aligned.m16n8k16.row.col.f32.f16.f16.f32 "
                            "{%0,%1,%2,%3}, {%4,%5,%6,%7}, {%8,%9}, {%0,%1,%2,%3};\n"
                            : "+f"(acc[mt][nt][0]), "+f"(acc[mt][nt][1]),
                              "+f"(acc[mt][nt][2]), "+f"(acc[mt][nt][3])
                            : "r"(a[mt][0]), "r"(a[mt][1]), "r"(a[mt][2]), "r"(a[mt][3]),
                              "r"(bq[half * 2]), "r"(bq[half * 2 + 1]));
                    }
                }
            }
        }
        __syncthreads();
    }

    // epilogue: apply mod_scale * demod[b, co] here
    const int h = h0 + warp_n;
    #pragma unroll
    for (int mt = 0; mt < 2; mt++) {
        int co_lo = co_base + warp_m * 32 + mt * 16 + g;
        float f0 = MOD_SCALE * __ldg(&g_demod[b * COUT_ + co_lo]);
        float f1 = MOD_SCALE * __ldg(&g_demod[b * COUT_ + co_lo + 8]);
        #pragma unroll
        for (int nt = 0; nt < 8; nt++) {
            int w = nt * 8 + tig * 2;
            float* p0 = out + (((size_t)(b * COUT_ + co_lo)) * H_ + h) * W_ + w;
            *(float2*)p0 = make_float2(acc[mt][nt][0] * f0, acc[mt][nt][1] * f0);
            float* p1 = p0 + (size_t)8 * H_ * W_;
            *(float2*)p1 = make_float2(acc[mt][nt][2] * f1, acc[mt][nt][3] * f1);
        }
    }
}

// ---------------------------------------------------------------------------
extern "C" void kernel_launch(void* const* d_in, const int* in_sizes, int n_in,
                              void* d_out, int out_size) {
    const float* x       = (const float*)d_in[0];
    const float* style   = (const float*)d_in[1];
    const float* weight  = (const float*)d_in[2];
    const float* style_w = (const float*)d_in[3];
    const float* style_b = (const float*)d_in[4];
    float* out = (float*)d_out;

    cudaFuncSetAttribute(k_conv, cudaFuncAttributeMaxDynamicSharedMemorySize, SMEM_TOTAL);

    k_wcvt<<<32, 256>>>(weight);               // weights fp16 + wsq (fused)
    k_sproj_demod<<<B_, 256>>>(style, style_w, style_b);

    dim3 gx(4, 64, 16);
    k_xcvt<<<gx, 256>>>(x);

    dim3 gc(H_ / 2, COUT_ / 128, B_);
    k_conv<<<gc, 256, SMEM_TOTAL>>>(out);
}

// round 15
// speedup vs baseline: 1.3982x; 1.0072x over previous
#include <cuda_runtime.h>
#include <cuda_fp16.h>
#include <cstdint>

#define B_    16
#define CIN_  256
#define COUT_ 256
#define H_    64
#define W_    64
#define SDIM_ 512

#define MOD_SCALE (1.0f / 48.0f)
#define SCALE2    (1.0f / 2304.0f)

// scratch
__device__ float g_s[B_ * CIN_];
__device__ float g_demod[B_ * COUT_];
__device__ float g_wsq[COUT_ * CIN_];
__device__ __half g_wth[(size_t)9 * COUT_ * CIN_];        // [tap][co][ci], batch-free
__device__ __half g_xh[(size_t)B_ * H_ * W_ * CIN_];      // NHWC fp16 of x * s[b,ci]

__device__ __forceinline__ uint32_t h2_bits(__half2 h) {
    union { __half2 h; uint32_t u; } c;
    c.h = h;
    return c.u;
}

// ---------------------------------------------------------------------------
// K_wcvt: fused batch-free weight convert + wsq. grid (32), block 256.
__global__ void k_wcvt(const float* __restrict__ weight) {
    const int tid = threadIdx.x;
    const int co = blockIdx.x * 8 + (tid >> 5);
    const int oct = tid & 31;

    float w[72];
    {
        const float4* wp = (const float4*)(weight + (size_t)co * 2304 + oct * 72);
        #pragma unroll
        for (int i = 0; i < 18; i++) {
            float4 v = wp[i];
            w[i * 4 + 0] = v.x; w[i * 4 + 1] = v.y; w[i * 4 + 2] = v.z; w[i * 4 + 3] = v.w;
        }
    }
    __half* ob = g_wth + (size_t)co * CIN_ + oct * 8;
    #pragma unroll
    for (int tap = 0; tap < 9; tap++) {
        uint32_t u[4];
        #pragma unroll
        for (int j2 = 0; j2 < 4; j2++) {
            u[j2] = h2_bits(__floats2half2_rn(w[(2 * j2) * 9 + tap],
                                              w[(2 * j2 + 1) * 9 + tap]));
        }
        *(uint4*)(ob + (size_t)tap * COUT_ * CIN_) = make_uint4(u[0], u[1], u[2], u[3]);
    }
    float q[8];
    #pragma unroll
    for (int j = 0; j < 8; j++) {
        float s = 0.f;
        #pragma unroll
        for (int t = 0; t < 9; t++) { float v = w[j * 9 + t]; s += v * v; }
        q[j] = s;
    }
    float4* wq = (float4*)(g_wsq + co * CIN_ + oct * 8);
    wq[0] = make_float4(q[0], q[1], q[2], q[3]);
    wq[1] = make_float4(q[4], q[5], q[6], q[7]);
}

// ---------------------------------------------------------------------------
// K_sd: fused style projection + demod. grid = B_, block = 256.
__global__ void k_sproj_demod(const float* __restrict__ style,
                              const float* __restrict__ style_w,
                              const float* __restrict__ style_b) {
    __shared__ float st[SDIM_];
    __shared__ float s2[CIN_];
    const int b = blockIdx.x, tid = threadIdx.x;
    for (int k = tid; k < SDIM_; k += 256)
        st[k] = style[b * SDIM_ + k];
    __syncthreads();
    float acc = style_b[tid];
    #pragma unroll 8
    for (int k = 0; k < SDIM_; k++)
        acc += st[k] * style_w[k * CIN_ + tid];
    g_s[b * CIN_ + tid] = acc;
    s2[tid] = acc * acc;
    __syncthreads();
    float acc2 = 0.f;
    const float* wq = g_wsq + tid * CIN_;
    #pragma unroll 8
    for (int ci = 0; ci < CIN_; ci++)
        acc2 += s2[ci] * wq[ci];
    g_demod[b * COUT_ + tid] = rsqrtf(acc2 * SCALE2 + 1e-8f);
}

// ---------------------------------------------------------------------------
// K_xcvt: NCHW fp32 -> NHWC fp16, folding in s[b,ci]; ci-pair half2 transpose.
#define XPAD 72
__global__ void __launch_bounds__(256)
k_xcvt(const float* __restrict__ x) {
    __shared__ __half xsp[64 * XPAD];
    __shared__ float sS[64];
    const int b = blockIdx.z, h = blockIdx.y, ci0 = blockIdx.x * 64;
    const int tid = threadIdx.x;
    const float* xp = x + ((size_t)(b * CIN_ + ci0) * H_ + h) * W_;

    if (tid < 64) sS[tid] = g_s[b * CIN_ + ci0 + tid];
    __syncthreads();

    #pragma unroll
    for (int i = 0; i < 8; i++) {
        int idx = tid + i * 256;                // 0..2047
        int cp = idx >> 6, w = idx & 63;
        int ci = cp * 2;
        float v0 = xp[(size_t)ci * (H_ * W_) + w] * sS[ci];
        float v1 = xp[(size_t)(ci + 1) * (H_ * W_) + w] * sS[ci + 1];
        *(__half2*)&xsp[w * XPAD + ci] = __floats2half2_rn(v0, v1);
    }
    __syncthreads();

    __half* op = g_xh + (((size_t)b * H_ + h) * W_) * CIN_ + ci0;
    #pragma unroll
    for (int i = 0; i < 2; i++) {
        int idx = tid + i * 256;
        int w = idx >> 3, j = idx & 7;
        uint4 v = *(const uint4*)&xsp[w * XPAD + j * 8];
        *(uint4*)(op + (size_t)w * CIN_ + j * 8) = v;
    }
}

// ---------------------------------------------------------------------------
// K_conv: 3-stage-pipelined implicit-GEMM, mma.sync.m16n8k16 fp16.
// CTA tile: M=64 co x N=128 px (2 rows x 64 cols). 8 warps = 2M x 4N,
// warp tile 32co x 32px (acc 32). One __syncthreads per chunk.
// grid (32, 4, 16).
#define KC 16
#define NC (CIN_ / KC)                 // 16 chunks
#define XS_BYTES (264 * KC * 2)        // 8448
#define WS_BYTES (9 * 64 * KC * 2)     // 18432
#define STAGE_BYTES (XS_BYTES + WS_BYTES)   // 26880
#define SMEM_TOTAL (3 * STAGE_BYTES)        // 80640

__global__ void __launch_bounds__(256, 2)
k_conv(float* __restrict__ out) {
    extern __shared__ char smem[];
    const uint32_t smem_u = (uint32_t)__cvta_generic_to_shared(smem);

    const int tid = threadIdx.x;
    const int lane = tid & 31, wid = tid >> 5;
    const int warp_m = wid >> 2;           // 0..1
    const int warp_n = wid & 3;            // 0..3
    const int g = lane >> 2, tig = lane & 3;

    const int h0 = blockIdx.x * 2;
    const int co_base = blockIdx.y * 64;
    const int b = blockIdx.z;

    const __half* wtb = g_wth + (size_t)co_base * CIN_;
    const __half* xhb = g_xh + (size_t)b * H_ * W_ * CIN_;

    // B staging geometry (closed form): unit u = px*2+hl, px = (tid>>1)+k*128
    const int co_t = tid >> 1, hl = tid & 1;
    uint32_t b_goff[3];
    int b_sz[3];
    #pragma unroll
    for (int k = 0; k < 3; k++) {
        int px = co_t + k * 128;
        int r = px / 66, cc = px - r * 66;
        int gh = h0 - 1 + r, gw = cc - 1;
        bool ok = ((unsigned)gh < (unsigned)H_) && ((unsigned)gw < (unsigned)W_);
        int ghc = ok ? gh : 0, gwc = ok ? gw : 0;
        b_goff[k] = (uint32_t)((ghc * W_ + gwc) * CIN_ + hl * 8);
        b_sz[k] = ok ? 16 : 0;
    }
    const uint32_t swzB = (uint32_t)((hl ^ ((co_t >> 2) & 1)) << 4);

    float acc[2][4][4];
    #pragma unroll
    for (int mt = 0; mt < 2; mt++)
        #pragma unroll
        for (int nt = 0; nt < 4; nt++)
            #pragma unroll
            for (int q = 0; q < 4; q++) acc[mt][nt][q] = 0.f;

    auto issue = [&](int c, int s) {
        const uint32_t stage = smem_u + s * STAGE_BYTES;
        // A: 1152 16B units -> wsT[tap][co(64)][ci]
        #pragma unroll
        for (int j = 0; j < 5; j++) {
            int u = tid + j * 256;
            if (j < 4 || u < 1152) {
                int row = u >> 1, ah = u & 1;       // row = tap*64+co
                int tap = row >> 6, co = row & 63;
                const __half* src = wtb + ((size_t)tap * COUT_ + co) * CIN_ + c * KC + ah * 8;
                uint32_t dst = stage + XS_BYTES + row * 32 + ((ah ^ ((co >> 2) & 1)) << 4);
                asm volatile("cp.async.cg.shared.global [%0], [%1], 16;"
                             :: "r"(dst), "l"(src));
            }
        }
        // B: 528 16B units -> xs[px(264)][ci]
        const __half* bsrc = xhb + c * KC;
        const uint32_t xsu = stage + co_t * 32 + swzB;
        #pragma unroll
        for (int k = 0; k < 2; k++) {
            asm volatile("cp.async.cg.shared.global [%0], [%1], 16, %2;"
                         :: "r"(xsu + k * 4096), "l"(bsrc + b_goff[k]), "r"(b_sz[k]));
        }
        if (tid < 16) {
            asm volatile("cp.async.cg.shared.global [%0], [%1], 16, %2;"
                         :: "r"(xsu + 2 * 4096), "l"(bsrc + b_goff[2]), "r"(b_sz[2]));
        }
        asm volatile("cp.async.commit_group;");
    };

    issue(0, 0);
    issue(1, 1);

    // ldmatrix lane geometry (A vs B distinct)
    const int laneRowA = (lane & 7) + (((lane >> 3) & 1) << 3);
    const uint32_t kA = (uint32_t)(((lane >> 4) & 1) << 4);
    const int laneRowB = (lane & 7) + ((lane >> 4) << 3);
    const uint32_t kB = (uint32_t)(((lane >> 3) & 1) << 4);

    const int rB = warp_n >> 1;            // warp row 0/1
    const int cB = (warp_n & 1) * 32;      // warp col base

    int sc = 0;   // c % 3
    for (int c = 0; c < NC; c++) {
        __syncthreads();                   // all warps done computing chunk c-1
        int s2 = sc + 2; if (s2 >= 3) s2 -= 3;
        if (c + 2 < NC) {
            issue(c + 2, s2);
            asm volatile("cp.async.wait_group 2;" ::: "memory");
        } else if (c + 1 < NC) {
            asm volatile("cp.async.wait_group 1;" ::: "memory");
        } else {
            asm volatile("cp.async.wait_group 0;" ::: "memory");
        }

        const uint32_t xs_u2 = smem_u + sc * STAGE_BYTES;
        const uint32_t ws_u2 = xs_u2 + XS_BYTES;

        #pragma unroll
        for (int tap = 0; tap < 9; tap++) {
            const int dh = tap / 3, dw = tap - dh * 3;

            uint32_t a[2][4];
            #pragma unroll
            for (int mt = 0; mt < 2; mt++) {
                int rowA = tap * 64 + warp_m * 32 + mt * 16 + laneRowA;
                uint32_t addrA = ws_u2 + rowA * 32 + (kA ^ ((rowA & 4) << 2));
                asm volatile("ldmatrix.sync.aligned.m8n8.x4.shared.b16 "
                             "{%0,%1,%2,%3}, [%4];"
                             : "=r"(a[mt][0]), "=r"(a[mt][1]),
                               "=r"(a[mt][2]), "=r"(a[mt][3])
                             : "r"(addrA));
            }
            const int rowoff = (rB + dh) * 66 + dw + cB;
            #pragma unroll
            for (int ntp = 0; ntp < 2; ntp++) {
                int pxl = rowoff + ntp * 16 + laneRowB;
                uint32_t addrB = xs_u2 + pxl * 32 + (kB ^ ((pxl & 4) << 2));
                uint32_t bq[4];
                asm volatile("ldmatrix.sync.aligned.m8n8.x4.shared.b16 "
                             "{%0,%1,%2,%3}, [%4];"
                             : "=r"(bq[0]), "=r"(bq[1]), "=r"(bq[2]), "=r"(bq[3])
                             : "r"(addrB));
                #pragma unroll
                for (int half = 0; half < 2; half++) {
                    int nt = ntp * 2 + half;
                    #pragma unroll
                    for (int mt = 0; mt < 2; mt++) {
                        asm volatile(
                            "mma.sync.aligned.m16n8k16.row.col.f32.f16.f16.f32 "
                            "{%0,%1,%2,%3}, {%4,%5,%6,%7}, {%8,%9}, {%0,%1,%2,%3};\n"
                            : "+f"(acc[mt][nt][0]), "+f"(acc[mt][nt][1]),
                              "+f"(acc[mt][nt][2]), "+f"(acc[mt][nt][3])
                            : "r"(a[mt][0]), "r"(a[mt][1]), "r"(a[mt][2]), "r"(a[mt][3]),
                              "r"(bq[half * 2]), "r"(bq[half * 2 + 1]));
                    }
                }
            }
        }
        sc = (sc + 1 == 3) ? 0 : sc + 1;
    }

    // epilogue: apply mod_scale * demod[b, co]
    const int h = h0 + rB;
    #pragma unroll
    for (int mt = 0; mt < 2; mt++) {
        int co_lo = co_base + warp_m * 32 + mt * 16 + g;
        float f0 = MOD_SCALE * __ldg(&g_demod[b * COUT_ + co_lo]);
        float f1 = MOD_SCALE * __ldg(&g_demod[b * COUT_ + co_lo + 8]);
        #pragma unroll
        for (int nt = 0; nt < 4; nt++) {
            int w = cB + nt * 8 + tig * 2;
            float* p0 = out + (((size_t)(b * COUT_ + co_lo)) * H_ + h) * W_ + w;
            *(float2*)p0 = make_float2(acc[mt][nt][0] * f0, acc[mt][nt][1] * f0);
            float* p1 = p0 + (size_t)8 * H_ * W_;
            *(float2*)p1 = make_float2(acc[mt][nt][2] * f1, acc[mt][nt][3] * f1);
        }
    }
}

// ---------------------------------------------------------------------------
extern "C" void kernel_launch(void* const* d_in, const int* in_sizes, int n_in,
                              void* d_out, int out_size) {
    const float* x       = (const float*)d_in[0];
    const float* style   = (const float*)d_in[1];
    const float* weight  = (const float*)d_in[2];
    const float* style_w = (const float*)d_in[3];
    const float* style_b = (const float*)d_in[4];
    float* out = (float*)d_out;

    cudaFuncSetAttribute(k_conv, cudaFuncAttributeMaxDynamicSharedMemorySize, SMEM_TOTAL);

    k_wcvt<<<32, 256>>>(weight);
    k_sproj_demod<<<B_, 256>>>(style, style_w, style_b);

    dim3 gx(4, 64, 16);
    k_xcvt<<<gx, 256>>>(x);

    dim3 gc(32, 4, 16);
    k_conv<<<gc, 256, SMEM_TOTAL>>>(out);
}

// round 16
// speedup vs baseline: 1.4310x; 1.0235x over previous
#include <cuda_runtime.h>
#include <cuda_fp16.h>
#include <cstdint>

#define B_    16
#define CIN_  256
#define COUT_ 256
#define H_    64
#define W_    64
#define SDIM_ 512

#define MOD_SCALE (1.0f / 48.0f)
#define SCALE2    (1.0f / 2304.0f)

// scratch
__device__ float g_s[B_ * CIN_];
__device__ float g_demod[B_ * COUT_];
__device__ float g_wsq[COUT_ * CIN_];
__device__ __half g_wth[(size_t)9 * COUT_ * CIN_];        // [tap][co][ci], batch-free
__device__ __half g_xh[(size_t)B_ * H_ * W_ * CIN_];      // NHWC fp16 of x * s[b,ci]

__device__ __forceinline__ uint32_t h2_bits(__half2 h) {
    union { __half2 h; uint32_t u; } c;
    c.h = h;
    return c.u;
}

// ---------------------------------------------------------------------------
// K_wcvt: fused batch-free weight convert + wsq. grid (32), block 256.
__global__ void k_wcvt(const float* __restrict__ weight) {
    const int tid = threadIdx.x;
    const int co = blockIdx.x * 8 + (tid >> 5);
    const int oct = tid & 31;

    float w[72];
    {
        const float4* wp = (const float4*)(weight + (size_t)co * 2304 + oct * 72);
        #pragma unroll
        for (int i = 0; i < 18; i++) {
            float4 v = wp[i];
            w[i * 4 + 0] = v.x; w[i * 4 + 1] = v.y; w[i * 4 + 2] = v.z; w[i * 4 + 3] = v.w;
        }
    }
    __half* ob = g_wth + (size_t)co * CIN_ + oct * 8;
    #pragma unroll
    for (int tap = 0; tap < 9; tap++) {
        uint32_t u[4];
        #pragma unroll
        for (int j2 = 0; j2 < 4; j2++) {
            u[j2] = h2_bits(__floats2half2_rn(w[(2 * j2) * 9 + tap],
                                              w[(2 * j2 + 1) * 9 + tap]));
        }
        *(uint4*)(ob + (size_t)tap * COUT_ * CIN_) = make_uint4(u[0], u[1], u[2], u[3]);
    }
    float q[8];
    #pragma unroll
    for (int j = 0; j < 8; j++) {
        float s = 0.f;
        #pragma unroll
        for (int t = 0; t < 9; t++) { float v = w[j * 9 + t]; s += v * v; }
        q[j] = s;
    }
    float4* wq = (float4*)(g_wsq + co * CIN_ + oct * 8);
    wq[0] = make_float4(q[0], q[1], q[2], q[3]);
    wq[1] = make_float4(q[4], q[5], q[6], q[7]);
}

// ---------------------------------------------------------------------------
// K_sd: fused style projection + demod. grid = B_, block = 256.
__global__ void k_sproj_demod(const float* __restrict__ style,
                              const float* __restrict__ style_w,
                              const float* __restrict__ style_b) {
    __shared__ float st[SDIM_];
    __shared__ float s2[CIN_];
    const int b = blockIdx.x, tid = threadIdx.x;
    for (int k = tid; k < SDIM_; k += 256)
        st[k] = style[b * SDIM_ + k];
    __syncthreads();
    float acc = style_b[tid];
    #pragma unroll 8
    for (int k = 0; k < SDIM_; k++)
        acc += st[k] * style_w[k * CIN_ + tid];
    g_s[b * CIN_ + tid] = acc;
    s2[tid] = acc * acc;
    __syncthreads();
    float acc2 = 0.f;
    const float* wq = g_wsq + tid * CIN_;
    #pragma unroll 8
    for (int ci = 0; ci < CIN_; ci++)
        acc2 += s2[ci] * wq[ci];
    g_demod[b * COUT_ + tid] = rsqrtf(acc2 * SCALE2 + 1e-8f);
}

// ---------------------------------------------------------------------------
// K_xcvt: NCHW fp32 -> NHWC fp16, folding in s[b,ci]; ci-pair half2 transpose.
#define XPAD 72
__global__ void __launch_bounds__(256)
k_xcvt(const float* __restrict__ x) {
    __shared__ __half xsp[64 * XPAD];
    __shared__ float sS[64];
    const int b = blockIdx.z, h = blockIdx.y, ci0 = blockIdx.x * 64;
    const int tid = threadIdx.x;
    const float* xp = x + ((size_t)(b * CIN_ + ci0) * H_ + h) * W_;

    if (tid < 64) sS[tid] = g_s[b * CIN_ + ci0 + tid];
    __syncthreads();

    #pragma unroll
    for (int i = 0; i < 8; i++) {
        int idx = tid + i * 256;                // 0..2047
        int cp = idx >> 6, w = idx & 63;
        int ci = cp * 2;
        float v0 = xp[(size_t)ci * (H_ * W_) + w] * sS[ci];
        float v1 = xp[(size_t)(ci + 1) * (H_ * W_) + w] * sS[ci + 1];
        *(__half2*)&xsp[w * XPAD + ci] = __floats2half2_rn(v0, v1);
    }
    __syncthreads();

    __half* op = g_xh + (((size_t)b * H_ + h) * W_) * CIN_ + ci0;
    #pragma unroll
    for (int i = 0; i < 2; i++) {
        int idx = tid + i * 256;
        int w = idx >> 3, j = idx & 7;
        uint4 v = *(const uint4*)&xsp[w * XPAD + j * 8];
        *(uint4*)(op + (size_t)w * CIN_ + j * 8) = v;
    }
}

// ---------------------------------------------------------------------------
// K_conv: CUTLASS-shape implicit-GEMM, mma.sync.m16n8k16 fp16.
// CTA = 128 threads (4 warps, 2M x 2N). Block tile 128co x 128px (2r x 64w).
// Warp tile 64co x 64px -> acc[4][8][4] = 128 regs; bytes/HMMA = 128.
// Double-buffered cp.async, XOR swizzle, ldmatrix. grid (32, 2, 16).
#define KC 16
#define NC (CIN_ / KC)                 // 16
#define XS_BYTES (264 * KC * 2)        // 8448
#define WS_BYTES (9 * 128 * KC * 2)    // 36864
#define STAGE_BYTES (XS_BYTES + WS_BYTES)   // 45312
#define SMEM_TOTAL (2 * STAGE_BYTES)        // 90624

__global__ void __launch_bounds__(128, 2)
k_conv(float* __restrict__ out) {
    extern __shared__ char smem[];
    const uint32_t smem_u = (uint32_t)__cvta_generic_to_shared(smem);

    const int tid = threadIdx.x;
    const int lane = tid & 31, wid = tid >> 5;
    const int warp_m = wid >> 1;           // 0..1 -> 64 co
    const int warp_n = wid & 1;            // 0..1 -> h row
    const int g = lane >> 2, tig = lane & 3;

    const int h0 = blockIdx.x * 2;
    const int co_base = blockIdx.y * 128;
    const int b = blockIdx.z;

    const __half* wtb = g_wth + (size_t)co_base * CIN_;
    const __half* xhb = g_xh + (size_t)b * H_ * W_ * CIN_;

    // B staging: 528 16B units; u = tid + k*128 (k<4), tail u = 512+tid (tid<16)
    // px = (tid>>1) + 64k (+256 tail), hl = tid&1; swz constant per thread.
    const int hl = tid & 1;
    const int px_b = tid >> 1;
    const uint32_t swzB = (uint32_t)((hl ^ ((px_b >> 2) & 1)) << 4);
    uint32_t b_goff[5];
    int b_sz[5];
    #pragma unroll
    for (int k = 0; k < 5; k++) {
        int px = px_b + k * 64;            // k=4 -> 256 + px_b (tail, valid if tid<16)
        int r = px / 66, cc = px - r * 66;
        int gh = h0 - 1 + r, gw = cc - 1;
        bool ok = ((unsigned)gh < (unsigned)H_) && ((unsigned)gw < (unsigned)W_);
        int ghc = ok ? gh : 0, gwc = ok ? gw : 0;
        b_goff[k] = (uint32_t)((ghc * W_ + gwc) * CIN_ + hl * 8);
        b_sz[k] = ok ? 16 : 0;
    }

    float acc[4][8][4];
    #pragma unroll
    for (int mt = 0; mt < 4; mt++)
        #pragma unroll
        for (int nt = 0; nt < 8; nt++)
            #pragma unroll
            for (int q = 0; q < 4; q++) acc[mt][nt][q] = 0.f;

    auto issue = [&](int c, int s) {
        const uint32_t stage = smem_u + s * STAGE_BYTES;
        // A: 2304 16B units -> wsT[tap][co(128)][ci]; 18 per thread
        #pragma unroll
        for (int j = 0; j < 18; j++) {
            int u = tid + j * 128;
            int row = u >> 1, ah = u & 1;        // row = tap*128 + co
            int co = row & 127;
            const __half* src = wtb + ((size_t)(row >> 7) * COUT_ + co) * CIN_ + c * KC + ah * 8;
            uint32_t dst = stage + XS_BYTES + row * 32 + (uint32_t)((ah ^ ((co >> 2) & 1)) << 4);
            asm volatile("cp.async.cg.shared.global [%0], [%1], 16;"
                         :: "r"(dst), "l"(src));
        }
        // B: 528 16B units
        const __half* bsrc = xhb + c * KC;
        const uint32_t xsu = stage + px_b * 32 + swzB;
        #pragma unroll
        for (int k = 0; k < 4; k++) {
            asm volatile("cp.async.cg.shared.global [%0], [%1], 16, %2;"
                         :: "r"(xsu + k * 2048), "l"(bsrc + b_goff[k]), "r"(b_sz[k]));
        }
        if (tid < 16) {
            asm volatile("cp.async.cg.shared.global [%0], [%1], 16, %2;"
                         :: "r"(xsu + 4 * 2048), "l"(bsrc + b_goff[4]), "r"(b_sz[4]));
        }
        asm volatile("cp.async.commit_group;");
    };

    issue(0, 0);

    // ldmatrix lane geometry (A vs B distinct)
    const int laneRowA = (lane & 7) + (((lane >> 3) & 1) << 3);
    const uint32_t kA = (uint32_t)(((lane >> 4) & 1) << 4);
    const int laneRowB = (lane & 7) + ((lane >> 4) << 3);
    const uint32_t kB = (uint32_t)(((lane >> 3) & 1) << 4);

    for (int c = 0; c < NC; c++) {
        if (c + 1 < NC) {
            issue(c + 1, (c + 1) & 1);
            asm volatile("cp.async.wait_group 1;" ::: "memory");
        } else {
            asm volatile("cp.async.wait_group 0;" ::: "memory");
        }
        __syncthreads();

        const uint32_t xs_u2 = smem_u + (c & 1) * STAGE_BYTES;
        const uint32_t ws_u2 = xs_u2 + XS_BYTES;

        #pragma unroll
        for (int tap = 0; tap < 9; tap++) {
            const int dh = tap / 3, dw = tap - dh * 3;

            // A fragments: 4 m-tiles of 16 co
            uint32_t a[4][4];
            #pragma unroll
            for (int mt = 0; mt < 4; mt++) {
                int rowA = tap * 128 + warp_m * 64 + mt * 16 + laneRowA;
                uint32_t addrA = ws_u2 + rowA * 32 + (kA ^ ((rowA & 4) << 2));
                asm volatile("ldmatrix.sync.aligned.m8n8.x4.shared.b16 "
                             "{%0,%1,%2,%3}, [%4];"
                             : "=r"(a[mt][0]), "=r"(a[mt][1]),
                               "=r"(a[mt][2]), "=r"(a[mt][3])
                             : "r"(addrA));
            }
            // B fragments: 4 n-groups of 16 px
            const int rowoff = (warp_n + dh) * 66 + dw;
            uint32_t bq[4][4];
            #pragma unroll
            for (int ntp = 0; ntp < 4; ntp++) {
                int pxl = rowoff + ntp * 16 + laneRowB;
                uint32_t addrB = xs_u2 + pxl * 32 + (kB ^ ((pxl & 4) << 2));
                asm volatile("ldmatrix.sync.aligned.m8n8.x4.shared.b16 "
                             "{%0,%1,%2,%3}, [%4];"
                             : "=r"(bq[ntp][0]), "=r"(bq[ntp][1]),
                               "=r"(bq[ntp][2]), "=r"(bq[ntp][3])
                             : "r"(addrB));
            }
            // 32 mma
            #pragma unroll
            for (int ntp = 0; ntp < 4; ntp++) {
                #pragma unroll
                for (int half = 0; half < 2; half++) {
                    int nt = ntp * 2 + half;
                    #pragma unroll
                    for (int mt = 0; mt < 4; mt++) {
                        asm volatile(
                            "mma.sync.aligned.m16n8k16.row.col.f32.f16.f16.f32 "
                            "{%0,%1,%2,%3}, {%4,%5,%6,%7}, {%8,%9}, {%0,%1,%2,%3};\n"
                            : "+f"(acc[mt][nt][0]), "+f"(acc[mt][nt][1]),
                              "+f"(acc[mt][nt][2]), "+f"(acc[mt][nt][3])
                            : "r"(a[mt][0]), "r"(a[mt][1]), "r"(a[mt][2]), "r"(a[mt][3]),
                              "r"(bq[ntp][half * 2]), "r"(bq[ntp][half * 2 + 1]));
                    }
                }
            }
        }
        __syncthreads();
    }

    // epilogue: apply mod_scale * demod[b, co]
    const int h = h0 + warp_n;
    #pragma unroll
    for (int mt = 0; mt < 4; mt++) {
        int co_lo = co_base + warp_m * 64 + mt * 16 + g;
        float f0 = MOD_SCALE * __ldg(&g_demod[b * COUT_ + co_lo]);
        float f1 = MOD_SCALE * __ldg(&g_demod[b * COUT_ + co_lo + 8]);
        #pragma unroll
        for (int nt = 0; nt < 8; nt++) {
            int w = nt * 8 + tig * 2;
            float* p0 = out + (((size_t)(b * COUT_ + co_lo)) * H_ + h) * W_ + w;
            *(float2*)p0 = make_float2(acc[mt][nt][0] * f0, acc[mt][nt][1] * f0);
            float* p1 = p0 + (size_t)8 * H_ * W_;
            *(float2*)p1 = make_float2(acc[mt][nt][2] * f1, acc[mt][nt][3] * f1);
        }
    }
}

// ---------------------------------------------------------------------------
extern "C" void kernel_launch(void* const* d_in, const int* in_sizes, int n_in,
                              void* d_out, int out_size) {
    const float* x       = (const float*)d_in[0];
    const float* style   = (const float*)d_in[1];
    const float* weight  = (const float*)d_in[2];
    const float* style_w = (const float*)d_in[3];
    const float* style_b = (const float*)d_in[4];
    float* out = (float*)d_out;

    cudaFuncSetAttribute(k_conv, cudaFuncAttributeMaxDynamicSharedMemorySize, SMEM_TOTAL);

    k_wcvt<<<32, 256>>>(weight);
    k_sproj_demod<<<B_, 256>>>(style, style_w, style_b);

    dim3 gx(4, 64, 16);
    k_xcvt<<<gx, 256>>>(x);

    dim3 gc(32, 2, 16);
    k_conv<<<gc, 128, SMEM_TOTAL>>>(out);
}